// round 4
// baseline (speedup 1.0000x reference)
#include <cuda_runtime.h>
#include <math.h>

#define B_   8
#define S_   512
#define E_   512
#define H_   8
#define HD_  64
#define BS_  4096            // B_*S_
#define TOK_ 2097152         // BS_*E_
#define V1_  16000
#define V2_  8000

// ---------------- scratch (device globals: allocation-free) ----------------
__device__ float g_x[TOK_];
__device__ float g_y[TOK_];
__device__ float g_q[TOK_];
__device__ float g_k[TOK_];
__device__ float g_v[TOK_];
__device__ float g_att[TOK_];
__device__ float g_t[TOK_];
__device__ float g_h[TOK_];
__device__ float g_enc[TOK_];
__device__ float g_h1[TOK_];
__device__ float g_h2[TOK_];
__device__ float g_dec[TOK_];
__device__ float g_wp[9 * E_ * E_];          // 9 repacked [E, H*HD] weights
__device__ float g_hid[(size_t)BS_ * V1_];   // 4096 x 16000 classifier hidden

// ---------------- weight repack: [H][E][HD] -> [E][H*HD] ----------------
__global__ void repack_kernel(const float* __restrict__ w, float* __restrict__ wp) {
    int o = blockIdx.x * blockDim.x + threadIdx.x;   // 0 .. 262143
    int c = o & 511;            // h*64 + d
    int e = o >> 9;
    int h = c >> 6, d = c & 63;
    wp[o] = w[((h << 9) + e) * 64 + d];
}

// ---------------- embedding + positional encoding ----------------
__global__ void embed_kernel(const int* __restrict__ ids, const float* __restrict__ emb,
                             float* __restrict__ out) {
    int s = blockIdx.x, b = blockIdx.y;
    int id = ids[b * S_ + s];
    const float* er = emb + (size_t)id * E_;
    float* orow = out + ((size_t)b * S_ + s) * E_;
    const float scale = 22.627416997969522f;   // sqrt(512)
    for (int i = threadIdx.x; i < E_; i += blockDim.x) {
        int d = (i < 256) ? i : (i - 256);
        float rate = expf((float)d * (-9.210340371976184f / 256.f)); // 10000^{-d/256}
        float ang = (float)s * rate;
        float p = (i < 256) ? sinf(ang) : cosf(ang);
        orow[i] = er[i] * scale + p;
    }
}

// ---------------- SGEMM: C[M,N] = A[M,K] @ B[K,N] (+bias)(+relu) ----------------
// 128x128 block tile, BK=8, 256 threads, 8x8 per-thread micro-tile.
// Assumes M % 128 == 0 and K % 8 == 0 and N % 4 == 0 (true for all calls here).
__global__ void __launch_bounds__(256) sgemm_kernel(
    const float* __restrict__ A, const float* __restrict__ Bm,
    const float* __restrict__ bias, float* __restrict__ C,
    int M, int N, int K, int relu)
{
    __shared__ float As[8][128];
    __shared__ float Bs[8][128];
    const int tid  = threadIdx.x;
    const int row0 = blockIdx.y * 128;
    const int col0 = blockIdx.x * 128;

    const int arow = tid >> 1;
    const int acol = (tid & 1) << 2;
    const int brow = tid >> 5;
    const int bcol = (tid & 31) << 2;
    const int tx = tid & 15;
    const int ty = tid >> 4;

    const float* Aptr = A + (size_t)(row0 + arow) * K + acol;
    const float* Bptr = Bm + (size_t)brow * N + col0 + bcol;
    const bool bok = (col0 + bcol) < N;

    float acc[8][8];
    #pragma unroll
    for (int i = 0; i < 8; i++)
        #pragma unroll
        for (int j = 0; j < 8; j++) acc[i][j] = 0.f;

    for (int k0 = 0; k0 < K; k0 += 8) {
        float4 av = *(const float4*)Aptr;
        float4 bv = bok ? *(const float4*)Bptr : make_float4(0.f, 0.f, 0.f, 0.f);
        As[acol    ][arow] = av.x;
        As[acol + 1][arow] = av.y;
        As[acol + 2][arow] = av.z;
        As[acol + 3][arow] = av.w;
        *(float4*)&Bs[brow][bcol] = bv;
        __syncthreads();
        #pragma unroll
        for (int kk = 0; kk < 8; kk++) {
            float4 a0 = *(const float4*)&As[kk][ty * 8];
            float4 a1 = *(const float4*)&As[kk][ty * 8 + 4];
            float4 b0 = *(const float4*)&Bs[kk][tx * 8];
            float4 b1 = *(const float4*)&Bs[kk][tx * 8 + 4];
            float ar[8] = {a0.x, a0.y, a0.z, a0.w, a1.x, a1.y, a1.z, a1.w};
            float br[8] = {b0.x, b0.y, b0.z, b0.w, b1.x, b1.y, b1.z, b1.w};
            #pragma unroll
            for (int i = 0; i < 8; i++)
                #pragma unroll
                for (int j = 0; j < 8; j++)
                    acc[i][j] = fmaf(ar[i], br[j], acc[i][j]);
        }
        __syncthreads();
        Aptr += 8;
        Bptr += (size_t)8 * N;
    }

    #pragma unroll
    for (int i = 0; i < 8; i++) {
        int r = row0 + ty * 8 + i;
        float* Crow = C + (size_t)r * N;
        #pragma unroll
        for (int j = 0; j < 8; j += 4) {
            int c = col0 + tx * 8 + j;
            if (c < N) {
                float4 v = make_float4(acc[i][j], acc[i][j+1], acc[i][j+2], acc[i][j+3]);
                if (bias) {
                    v.x += bias[c];   v.y += bias[c+1];
                    v.z += bias[c+2]; v.w += bias[c+3];
                }
                if (relu) {
                    v.x = fmaxf(v.x, 0.f); v.y = fmaxf(v.y, 0.f);
                    v.z = fmaxf(v.z, 0.f); v.w = fmaxf(v.w, 0.f);
                }
                *(float4*)&Crow[c] = v;
            }
        }
    }
}

// ---------------- fused attention: one block per (b,h,q) ----------------
// Q,K,V,O layout: [b, s, h, d]  (elem offset = b*262144 + s*512 + h*64 + d)
__global__ void __launch_bounds__(128) attn_kernel(
    const float* __restrict__ Q, const float* __restrict__ K,
    const float* __restrict__ V, float* __restrict__ O, int causal)
{
    const int q = blockIdx.x;
    const int b = blockIdx.y >> 3;
    const int h = blockIdx.y & 7;
    const int tid = threadIdx.x;
    __shared__ float qs[64];
    __shared__ float w[512];
    __shared__ float smax[4], ssum[4];
    __shared__ float part[128];

    const size_t base = (size_t)b * 262144 + (size_t)h * 64;
    if (tid < 64) qs[tid] = Q[base + (size_t)q * 512 + tid];
    __syncthreads();

    const float scale = 0.044194173824159216f;   // 1/sqrt(512) — ref divides by sqrt(Sk)
    const int kmax = causal ? q : 511;
    float lk[4];
    float lmax = -1e30f;
    #pragma unroll
    for (int i = 0; i < 4; i++) {
        int k = tid + i * 128;
        float val = -1e30f;
        if (k <= kmax) {
            const float* Kr = K + base + (size_t)k * 512;
            float acc = 0.f;
            #pragma unroll
            for (int d = 0; d < 64; d += 4) {
                float4 kv = *(const float4*)(Kr + d);
                acc = fmaf(qs[d],   kv.x, acc);
                acc = fmaf(qs[d+1], kv.y, acc);
                acc = fmaf(qs[d+2], kv.z, acc);
                acc = fmaf(qs[d+3], kv.w, acc);
            }
            val = acc * scale;
        }
        lk[i] = val;
        lmax = fmaxf(lmax, val);
    }
    const int lane = tid & 31, wrp = tid >> 5;
    #pragma unroll
    for (int o = 16; o; o >>= 1) lmax = fmaxf(lmax, __shfl_xor_sync(0xffffffffu, lmax, o));
    if (!lane) smax[wrp] = lmax;
    __syncthreads();
    const float gmax = fmaxf(fmaxf(smax[0], smax[1]), fmaxf(smax[2], smax[3]));

    float lsum = 0.f;
    #pragma unroll
    for (int i = 0; i < 4; i++) {
        int k = tid + i * 128;
        float e = (k <= kmax) ? __expf(lk[i] - gmax) : 0.f;
        w[k] = e;
        lsum += e;
    }
    #pragma unroll
    for (int o = 16; o; o >>= 1) lsum += __shfl_xor_sync(0xffffffffu, lsum, o);
    if (!lane) ssum[wrp] = lsum;
    __syncthreads();                       // also makes all w[] visible
    const float inv = 1.f / (ssum[0] + ssum[1] + ssum[2] + ssum[3]);

    const int d = tid & 63, hh = tid >> 6;
    const float* Vb = V + base + d;
    float acc = 0.f;
    const int klim = kmax + 1;
    for (int k = hh; k < klim; k += 2)
        acc = fmaf(w[k], Vb[(size_t)k * 512], acc);
    part[tid] = acc;
    __syncthreads();
    if (tid < 64)
        O[base + (size_t)q * 512 + tid] = (part[tid] + part[tid + 64]) * inv;
}

// ---------------- residual + layernorm (+optional relu) ----------------
// out = [relu](LN(X + R)); rows of 512, eps = 1e-3 (keras default in ref)
__global__ void __launch_bounds__(128) ln_kernel(
    const float* __restrict__ X, const float* __restrict__ R,
    const float* __restrict__ g, const float* __restrict__ bet,
    float* __restrict__ O, int relu)
{
    const int row = blockIdx.x;
    const float* xr = X + (size_t)row * 512;
    const float* rr = R + (size_t)row * 512;
    float* orow = O + (size_t)row * 512;
    const int tid = threadIdx.x;
    float v[4];
    float s = 0.f, sq = 0.f;
    #pragma unroll
    for (int i = 0; i < 4; i++) {
        int idx = tid + i * 128;
        float t = xr[idx] + rr[idx];
        v[i] = t; s += t; sq = fmaf(t, t, sq);
    }
    __shared__ float ss[4], sqs[4];
    #pragma unroll
    for (int o = 16; o; o >>= 1) {
        s  += __shfl_xor_sync(0xffffffffu, s, o);
        sq += __shfl_xor_sync(0xffffffffu, sq, o);
    }
    const int lane = tid & 31, wrp = tid >> 5;
    if (!lane) { ss[wrp] = s; sqs[wrp] = sq; }
    __syncthreads();
    s  = ss[0] + ss[1] + ss[2] + ss[3];
    sq = sqs[0] + sqs[1] + sqs[2] + sqs[3];
    const float mean = s * (1.f / 512.f);
    const float var = sq * (1.f / 512.f) - mean * mean;
    const float invs = rsqrtf(var + 1e-3f);
    #pragma unroll
    for (int i = 0; i < 4; i++) {
        int idx = tid + i * 128;
        float o = (v[i] - mean) * invs * g[idx] + bet[idx];
        if (relu) o = fmaxf(o, 0.f);
        orow[idx] = o;
    }
}

// ---------------- host orchestration ----------------
static inline void gemm(const float* A, const float* Bm, const float* bias,
                        float* C, int M, int N, int K, int relu) {
    dim3 grid((N + 127) / 128, M / 128);
    sgemm_kernel<<<grid, 256>>>(A, Bm, bias, C, M, N, K, relu);
}

extern "C" void kernel_launch(void* const* d_in, const int* in_sizes, int n_in,
                              void* d_out, int out_size) {
    const int*   src_ids  = (const int*)  d_in[0];
    const int*   tgt_ids  = (const int*)  d_in[1];
    const float* src_emb  = (const float*)d_in[2];
    const float* tgt_emb  = (const float*)d_in[3];
    const float* enc_wk   = (const float*)d_in[4];
    const float* enc_wv   = (const float*)d_in[5];
    const float* enc_wq   = (const float*)d_in[6];
    const float* enc_dw   = (const float*)d_in[7];
    const float* enc_db   = (const float*)d_in[8];
    const float* enc_ffw  = (const float*)d_in[9];
    const float* enc_ffb  = (const float*)d_in[10];
    const float* enc_ln_g = (const float*)d_in[11];
    const float* enc_ln_b = (const float*)d_in[12];
    const float* dec_swk  = (const float*)d_in[13];
    const float* dec_swv  = (const float*)d_in[14];
    const float* dec_swq  = (const float*)d_in[15];
    const float* dec_sdw  = (const float*)d_in[16];
    const float* dec_sdb  = (const float*)d_in[17];
    const float* dec_cwk  = (const float*)d_in[18];
    const float* dec_cwv  = (const float*)d_in[19];
    const float* dec_cwq  = (const float*)d_in[20];
    const float* dec_cdw  = (const float*)d_in[21];
    const float* dec_cdb  = (const float*)d_in[22];
    const float* dec_ffw  = (const float*)d_in[23];
    const float* dec_ffb  = (const float*)d_in[24];
    const float* dec_ln_g = (const float*)d_in[25];
    const float* dec_ln_b = (const float*)d_in[26];
    const float* cls_w1   = (const float*)d_in[27];
    const float* cls_b1   = (const float*)d_in[28];
    const float* cls_w2   = (const float*)d_in[29];
    const float* cls_b2   = (const float*)d_in[30];
    float* out = (float*)d_out;

    float *px, *py, *pq, *pk, *pv, *pat, *pt, *ph, *penc, *ph1, *ph2, *pdec, *pwp, *phid;
    cudaGetSymbolAddress((void**)&px,   g_x);
    cudaGetSymbolAddress((void**)&py,   g_y);
    cudaGetSymbolAddress((void**)&pq,   g_q);
    cudaGetSymbolAddress((void**)&pk,   g_k);
    cudaGetSymbolAddress((void**)&pv,   g_v);
    cudaGetSymbolAddress((void**)&pat,  g_att);
    cudaGetSymbolAddress((void**)&pt,   g_t);
    cudaGetSymbolAddress((void**)&ph,   g_h);
    cudaGetSymbolAddress((void**)&penc, g_enc);
    cudaGetSymbolAddress((void**)&ph1,  g_h1);
    cudaGetSymbolAddress((void**)&ph2,  g_h2);
    cudaGetSymbolAddress((void**)&pdec, g_dec);
    cudaGetSymbolAddress((void**)&pwp,  g_wp);
    cudaGetSymbolAddress((void**)&phid, g_hid);

    const int WSZ = E_ * E_;   // 262144
    // repack all 9 per-head weight stacks into [E, H*HD]
    repack_kernel<<<512, 512>>>(enc_wq,  pwp + 0 * WSZ);
    repack_kernel<<<512, 512>>>(enc_wk,  pwp + 1 * WSZ);
    repack_kernel<<<512, 512>>>(enc_wv,  pwp + 2 * WSZ);
    repack_kernel<<<512, 512>>>(dec_swq, pwp + 3 * WSZ);
    repack_kernel<<<512, 512>>>(dec_swk, pwp + 4 * WSZ);
    repack_kernel<<<512, 512>>>(dec_swv, pwp + 5 * WSZ);
    repack_kernel<<<512, 512>>>(dec_cwq, pwp + 6 * WSZ);
    repack_kernel<<<512, 512>>>(dec_cwk, pwp + 7 * WSZ);
    repack_kernel<<<512, 512>>>(dec_cwv, pwp + 8 * WSZ);

    // embeddings + positional encoding
    embed_kernel<<<dim3(S_, B_), 128>>>(src_ids, src_emb, px);
    embed_kernel<<<dim3(S_, B_), 128>>>(tgt_ids, tgt_emb, py);

    dim3 agrid(512, 64);

    // ----- encoder block (self-attn is causal in the original) -----
    gemm(px, pwp + 0 * WSZ, nullptr, pq, BS_, 512, 512, 0);
    gemm(px, pwp + 1 * WSZ, nullptr, pk, BS_, 512, 512, 0);
    gemm(px, pwp + 2 * WSZ, nullptr, pv, BS_, 512, 512, 0);
    attn_kernel<<<agrid, 128>>>(pq, pk, pv, pat, 1);
    gemm(pat, enc_dw, enc_db, pt, BS_, 512, 512, 0);
    ln_kernel<<<BS_, 128>>>(px, pt, enc_ln_g, enc_ln_b, ph, 0);
    gemm(ph, enc_ffw, enc_ffb, pt, BS_, 512, 512, 0);
    ln_kernel<<<BS_, 128>>>(ph, pt, enc_ln_g, enc_ln_b, penc, 0);

    // ----- decoder self-attention -----
    gemm(py, pwp + 3 * WSZ, nullptr, pq, BS_, 512, 512, 0);
    gemm(py, pwp + 4 * WSZ, nullptr, pk, BS_, 512, 512, 0);
    gemm(py, pwp + 5 * WSZ, nullptr, pv, BS_, 512, 512, 0);
    attn_kernel<<<agrid, 128>>>(pq, pk, pv, pat, 1);
    gemm(pat, dec_sdw, dec_sdb, pt, BS_, 512, 512, 0);
    ln_kernel<<<BS_, 128>>>(py, pt, dec_ln_g, dec_ln_b, ph1, 0);

    // ----- decoder cross-attention (K,V from encoder out; Q from h1) -----
    gemm(ph1,  pwp + 6 * WSZ, nullptr, pq, BS_, 512, 512, 0);
    gemm(penc, pwp + 7 * WSZ, nullptr, pk, BS_, 512, 512, 0);
    gemm(penc, pwp + 8 * WSZ, nullptr, pv, BS_, 512, 512, 0);
    attn_kernel<<<agrid, 128>>>(pq, pk, pv, pat, 0);
    gemm(pat, dec_cdw, dec_cdb, pt, BS_, 512, 512, 0);
    ln_kernel<<<BS_, 128>>>(ph1, pt, dec_ln_g, dec_ln_b, ph2, 0);

    // ----- decoder FF + final (relu'ed) LN -----
    gemm(ph2, dec_ffw, dec_ffb, pt, BS_, 512, 512, 0);
    ln_kernel<<<BS_, 128>>>(ph2, pt, dec_ln_g, dec_ln_b, pdec, 1);

    // ----- classifier -----
    gemm(pdec, cls_w1, cls_b1, phid, BS_, V1_, 512, 1);     // relu
    gemm(phid, cls_w2, cls_b2, out,  BS_, V2_, V1_, 0);     // dominant GEMM
}

// round 6
// speedup vs baseline: 1.5521x; 1.5521x over previous
#include <cuda_runtime.h>
#include <math.h>
#include <stdint.h>

#define B_   8
#define S_   512
#define E_   512
#define BS_  4096            // B_*S_
#define TOK_ 2097152         // BS_*E_
#define V1_  16000
#define V2_  8000

// ---------------- scratch (device globals: allocation-free) ----------------
__device__ float g_x[TOK_];
__device__ float g_y[TOK_];
__device__ float g_q[TOK_];
__device__ float g_k[TOK_];
__device__ float g_v[TOK_];
__device__ float g_att[TOK_];
__device__ float g_t[TOK_];
__device__ float g_h[TOK_];
__device__ float g_enc[TOK_];
__device__ float g_h1[TOK_];
__device__ float g_h2[TOK_];
__device__ float g_dec[TOK_];
__device__ float g_wp[9 * E_ * E_];            // repacked per-head weights
__device__ float g_hid[(size_t)BS_ * V1_];     // 4096 x 16000 (tf32-rounded)
__device__ float g_w2r[(size_t)V1_ * V2_];     // tf32-rounded cls_w2 (512MB)

__device__ __forceinline__ float tf32r(float x) {
    float y;
    asm("cvt.rna.tf32.f32 %0, %1;" : "=f"(y) : "f"(x));
    return y;
}

// ---------------- weight repack: [H][E][HD] -> [E][H*HD] ----------------
__global__ void repack_kernel(const float* __restrict__ w, float* __restrict__ wp) {
    int o = blockIdx.x * blockDim.x + threadIdx.x;
    int c = o & 511;
    int e = o >> 9;
    int h = c >> 6, d = c & 63;
    wp[o] = w[((h << 9) + e) * 64 + d];
}

// ---------------- tf32 pre-round (for classifier-2 weights) ----------------
__global__ void round_kernel(const float4* __restrict__ in, float4* __restrict__ out, int n4) {
    int i = blockIdx.x * blockDim.x + threadIdx.x;
    int stride = gridDim.x * blockDim.x;
    for (; i < n4; i += stride) {
        float4 v = in[i];
        v.x = tf32r(v.x); v.y = tf32r(v.y); v.z = tf32r(v.z); v.w = tf32r(v.w);
        out[i] = v;
    }
}

// ---------------- embedding + positional encoding ----------------
__global__ void embed_kernel(const int* __restrict__ ids, const float* __restrict__ emb,
                             float* __restrict__ out) {
    int s = blockIdx.x, b = blockIdx.y;
    int id = ids[b * S_ + s];
    const float* er = emb + (size_t)id * E_;
    float* orow = out + ((size_t)b * S_ + s) * E_;
    const float scale = 22.627416997969522f;   // sqrt(512)
    for (int i = threadIdx.x; i < E_; i += blockDim.x) {
        int d = (i < 256) ? i : (i - 256);
        float rate = expf((float)d * (-9.210340371976184f / 256.f));
        float ang = (float)s * rate;
        float p = (i < 256) ? sinf(ang) : cosf(ang);
        orow[i] = er[i] * scale + p;
    }
}

// ---------------- fp32 SGEMM (small GEMMs + classifier-1) ----------------
__global__ void __launch_bounds__(256) sgemm_kernel(
    const float* __restrict__ A, const float* __restrict__ Bm,
    const float* __restrict__ bias, float* __restrict__ C,
    int M, int N, int K, int relu, int rnd)
{
    __shared__ float As[8][128];
    __shared__ float Bs[8][128];
    const int tid  = threadIdx.x;
    const int row0 = blockIdx.y * 128;
    const int col0 = blockIdx.x * 128;

    const int arow = tid >> 1;
    const int acol = (tid & 1) << 2;
    const int brow = tid >> 5;
    const int bcol = (tid & 31) << 2;
    const int tx = tid & 15;
    const int ty = tid >> 4;

    const float* Aptr = A + (size_t)(row0 + arow) * K + acol;
    const float* Bptr = Bm + (size_t)brow * N + col0 + bcol;
    const bool bok = (col0 + bcol) < N;

    float acc[8][8];
    #pragma unroll
    for (int i = 0; i < 8; i++)
        #pragma unroll
        for (int j = 0; j < 8; j++) acc[i][j] = 0.f;

    for (int k0 = 0; k0 < K; k0 += 8) {
        float4 av = *(const float4*)Aptr;
        float4 bv = bok ? *(const float4*)Bptr : make_float4(0.f, 0.f, 0.f, 0.f);
        As[acol    ][arow] = av.x;
        As[acol + 1][arow] = av.y;
        As[acol + 2][arow] = av.z;
        As[acol + 3][arow] = av.w;
        *(float4*)&Bs[brow][bcol] = bv;
        __syncthreads();
        #pragma unroll
        for (int kk = 0; kk < 8; kk++) {
            float4 a0 = *(const float4*)&As[kk][ty * 8];
            float4 a1 = *(const float4*)&As[kk][ty * 8 + 4];
            float4 b0 = *(const float4*)&Bs[kk][tx * 8];
            float4 b1 = *(const float4*)&Bs[kk][tx * 8 + 4];
            float ar[8] = {a0.x, a0.y, a0.z, a0.w, a1.x, a1.y, a1.z, a1.w};
            float br[8] = {b0.x, b0.y, b0.z, b0.w, b1.x, b1.y, b1.z, b1.w};
            #pragma unroll
            for (int i = 0; i < 8; i++)
                #pragma unroll
                for (int j = 0; j < 8; j++)
                    acc[i][j] = fmaf(ar[i], br[j], acc[i][j]);
        }
        __syncthreads();
        Aptr += 8;
        Bptr += (size_t)8 * N;
    }

    #pragma unroll
    for (int i = 0; i < 8; i++) {
        int r = row0 + ty * 8 + i;
        float* Crow = C + (size_t)r * N;
        #pragma unroll
        for (int j = 0; j < 8; j += 4) {
            int c = col0 + tx * 8 + j;
            if (c < N) {
                float4 v = make_float4(acc[i][j], acc[i][j+1], acc[i][j+2], acc[i][j+3]);
                if (bias) {
                    v.x += bias[c];   v.y += bias[c+1];
                    v.z += bias[c+2]; v.w += bias[c+3];
                }
                if (relu) {
                    v.x = fmaxf(v.x, 0.f); v.y = fmaxf(v.y, 0.f);
                    v.z = fmaxf(v.z, 0.f); v.w = fmaxf(v.w, 0.f);
                }
                if (rnd) {   // pre-round for downstream tf32 mma consumption
                    v.x = tf32r(v.x); v.y = tf32r(v.y);
                    v.z = tf32r(v.z); v.w = tf32r(v.w);
                }
                *(float4*)&Crow[c] = v;
            }
        }
    }
}

// ---------------- TF32 tensor-core GEMM (classifier-2) ----------------
// C[M,N] = A[M,K] @ B[K,N] + bias. Inputs must already be tf32-rounded.
// 128x128x32 block tile, 8 warps (64x32 warp tile), cp.async double buffer.
__device__ __forceinline__ void cp16(uint32_t dst, const void* src, int sbytes) {
    asm volatile("cp.async.cg.shared.global [%0], [%1], 16, %2;\n"
                 :: "r"(dst), "l"(src), "r"(sbytes));
}

__global__ void __launch_bounds__(256) tf32gemm_kernel(
    const float* __restrict__ A, const float* __restrict__ Bm,
    const float* __restrict__ bias, float* __restrict__ C,
    int M, int N, int K)
{
    extern __shared__ float smem[];
    // layout: As[2][128][36] then Bs[2][32][128]
    const uint32_t sb = (uint32_t)__cvta_generic_to_shared(smem);
    const int AS_ST = 4608;                // floats per A stage
    const int BS_OFF = 2 * 4608;           // float offset of Bs
    const int BS_ST = 4096;

    const int tid = threadIdx.x;
    const int lane = tid & 31, wid = tid >> 5;
    const int wm = wid >> 2, wn = wid & 3;       // 2x4 warp grid
    const int row0 = blockIdx.y * 128, col0 = blockIdx.x * 128;
    const int g = lane >> 2, tg = lane & 3;

    // fill assignments
    const int ar = tid >> 3, ac = (tid & 7) << 2;    // A: rows ar+32i, cols ac..ac+3
    const int br = tid >> 5, bc = (tid & 31) << 2;   // B: rows br+8i, cols bc..bc+3

    const int coln = col0 + bc;
    const int pb = (coln < N) ? 16 : 0;

    float acc[4][4][4];
    #pragma unroll
    for (int a = 0; a < 4; a++)
        #pragma unroll
        for (int b = 0; b < 4; b++)
            #pragma unroll
            for (int c = 0; c < 4; c++) acc[a][b][c] = 0.f;

    const int nst = K >> 5;

    // ---- stage fill macro-ish helpers (fully inlined) ----
    #define FILL_STAGE(T, ST)                                                        \
    do {                                                                             \
        const float* sA = A + (size_t)(row0 + ar) * K + (T) * 32 + ac;               \
        uint32_t dA = sb + (uint32_t)(((ST) * AS_ST + ar * 36 + ac) << 2);           \
        _Pragma("unroll")                                                            \
        for (int i = 0; i < 4; i++)                                                  \
            cp16(dA + (uint32_t)(i * 32 * 36 * 4), sA + (size_t)(i * 32) * K, 16);   \
        const float* sB = Bm + (size_t)((T) * 32 + br) * N + (pb ? coln : 0);        \
        uint32_t dB = sb + (uint32_t)((BS_OFF + (ST) * BS_ST + br * 128 + bc) << 2); \
        _Pragma("unroll")                                                            \
        for (int i = 0; i < 4; i++)                                                  \
            cp16(dB + (uint32_t)(i * 8 * 128 * 4), sB + (size_t)(i * 8) * N, pb);    \
        asm volatile("cp.async.commit_group;\n" ::);                                 \
    } while (0)

    FILL_STAGE(0, 0);

    for (int t = 0; t < nst; ++t) {
        const int st = t & 1;
        if (t + 1 < nst) {
            FILL_STAGE(t + 1, st ^ 1);
            asm volatile("cp.async.wait_group 1;\n" ::);
        } else {
            asm volatile("cp.async.wait_group 0;\n" ::);
        }
        __syncthreads();

        const float* as = smem + st * AS_ST;
        const float* bs = smem + BS_OFF + st * BS_ST;

        #pragma unroll
        for (int ks = 0; ks < 4; ks++) {
            const int k = ks * 8;
            uint32_t af[4][4], bf[4][2];
            #pragma unroll
            for (int mf = 0; mf < 4; mf++) {
                const uint32_t* p = (const uint32_t*)(as + (wm * 64 + mf * 16 + g) * 36 + k + tg);
                af[mf][0] = p[0];
                af[mf][1] = p[8 * 36];
                af[mf][2] = p[4];
                af[mf][3] = p[8 * 36 + 4];
            }
            #pragma unroll
            for (int nf = 0; nf < 4; nf++) {
                const uint32_t* p = (const uint32_t*)(bs + (k + tg) * 128 + wn * 32 + nf * 8 + g);
                bf[nf][0] = p[0];
                bf[nf][1] = p[4 * 128];
            }
            #pragma unroll
            for (int mf = 0; mf < 4; mf++)
                #pragma unroll
                for (int nf = 0; nf < 4; nf++) {
                    asm volatile(
                        "mma.sync.aligned.m16n8k8.row.col.f32.tf32.tf32.f32 "
                        "{%0,%1,%2,%3}, {%4,%5,%6,%7}, {%8,%9}, {%0,%1,%2,%3};"
                        : "+f"(acc[mf][nf][0]), "+f"(acc[mf][nf][1]),
                          "+f"(acc[mf][nf][2]), "+f"(acc[mf][nf][3])
                        : "r"(af[mf][0]), "r"(af[mf][1]), "r"(af[mf][2]), "r"(af[mf][3]),
                          "r"(bf[nf][0]), "r"(bf[nf][1]));
                }
        }
        __syncthreads();
    }
    #undef FILL_STAGE

    // epilogue
    #pragma unroll
    for (int mf = 0; mf < 4; mf++) {
        const int r = row0 + wm * 64 + mf * 16 + g;
        #pragma unroll
        for (int nf = 0; nf < 4; nf++) {
            const int c = col0 + wn * 32 + nf * 8 + 2 * tg;
            if (c < N) {
                const float b0 = bias ? bias[c] : 0.f;
                const float b1 = bias ? bias[c + 1] : 0.f;
                float* p0 = C + (size_t)r * N + c;
                float* p1 = C + (size_t)(r + 8) * N + c;
                p0[0] = acc[mf][nf][0] + b0;
                p0[1] = acc[mf][nf][1] + b1;
                p1[0] = acc[mf][nf][2] + b0;
                p1[1] = acc[mf][nf][3] + b1;
            }
        }
    }
}

// ---------------- fused attention: one block per (b,h,q) ----------------
__global__ void __launch_bounds__(128) attn_kernel(
    const float* __restrict__ Q, const float* __restrict__ K,
    const float* __restrict__ V, float* __restrict__ O, int causal)
{
    const int q = blockIdx.x;
    const int b = blockIdx.y >> 3;
    const int h = blockIdx.y & 7;
    const int tid = threadIdx.x;
    __shared__ float qs[64];
    __shared__ float w[512];
    __shared__ float smax[4], ssum[4];
    __shared__ float part[128];

    const size_t base = (size_t)b * 262144 + (size_t)h * 64;
    if (tid < 64) qs[tid] = Q[base + (size_t)q * 512 + tid];
    __syncthreads();

    const float scale = 0.044194173824159216f;   // 1/sqrt(512)
    const int kmax = causal ? q : 511;
    float lk[4];
    float lmax = -1e30f;
    #pragma unroll
    for (int i = 0; i < 4; i++) {
        int k = tid + i * 128;
        float val = -1e30f;
        if (k <= kmax) {
            const float* Kr = K + base + (size_t)k * 512;
            float acc = 0.f;
            #pragma unroll
            for (int d = 0; d < 64; d += 4) {
                float4 kv = *(const float4*)(Kr + d);
                acc = fmaf(qs[d],   kv.x, acc);
                acc = fmaf(qs[d+1], kv.y, acc);
                acc = fmaf(qs[d+2], kv.z, acc);
                acc = fmaf(qs[d+3], kv.w, acc);
            }
            val = acc * scale;
        }
        lk[i] = val;
        lmax = fmaxf(lmax, val);
    }
    const int lane = tid & 31, wrp = tid >> 5;
    #pragma unroll
    for (int o = 16; o; o >>= 1) lmax = fmaxf(lmax, __shfl_xor_sync(0xffffffffu, lmax, o));
    if (!lane) smax[wrp] = lmax;
    __syncthreads();
    const float gmax = fmaxf(fmaxf(smax[0], smax[1]), fmaxf(smax[2], smax[3]));

    float lsum = 0.f;
    #pragma unroll
    for (int i = 0; i < 4; i++) {
        int k = tid + i * 128;
        float e = (k <= kmax) ? __expf(lk[i] - gmax) : 0.f;
        w[k] = e;
        lsum += e;
    }
    #pragma unroll
    for (int o = 16; o; o >>= 1) lsum += __shfl_xor_sync(0xffffffffu, lsum, o);
    if (!lane) ssum[wrp] = lsum;
    __syncthreads();
    const float inv = 1.f / (ssum[0] + ssum[1] + ssum[2] + ssum[3]);

    const int d = tid & 63, hh = tid >> 6;
    const float* Vb = V + base + d;
    float acc = 0.f;
    const int klim = kmax + 1;
    for (int k = hh; k < klim; k += 2)
        acc = fmaf(w[k], Vb[(size_t)k * 512], acc);
    part[tid] = acc;
    __syncthreads();
    if (tid < 64)
        O[base + (size_t)q * 512 + tid] = (part[tid] + part[tid + 64]) * inv;
}

// ---------------- residual + layernorm (+optional relu) ----------------
__global__ void __launch_bounds__(128) ln_kernel(
    const float* __restrict__ X, const float* __restrict__ R,
    const float* __restrict__ g, const float* __restrict__ bet,
    float* __restrict__ O, int relu)
{
    const int row = blockIdx.x;
    const float* xr = X + (size_t)row * 512;
    const float* rr = R + (size_t)row * 512;
    float* orow = O + (size_t)row * 512;
    const int tid = threadIdx.x;
    float v[4];
    float s = 0.f, sq = 0.f;
    #pragma unroll
    for (int i = 0; i < 4; i++) {
        int idx = tid + i * 128;
        float t = xr[idx] + rr[idx];
        v[i] = t; s += t; sq = fmaf(t, t, sq);
    }
    __shared__ float ss[4], sqs[4];
    #pragma unroll
    for (int o = 16; o; o >>= 1) {
        s  += __shfl_xor_sync(0xffffffffu, s, o);
        sq += __shfl_xor_sync(0xffffffffu, sq, o);
    }
    const int lane = tid & 31, wrp = tid >> 5;
    if (!lane) { ss[wrp] = s; sqs[wrp] = sq; }
    __syncthreads();
    s  = ss[0] + ss[1] + ss[2] + ss[3];
    sq = sqs[0] + sqs[1] + sqs[2] + sqs[3];
    const float mean = s * (1.f / 512.f);
    const float var = sq * (1.f / 512.f) - mean * mean;
    const float invs = rsqrtf(var + 1e-3f);
    #pragma unroll
    for (int i = 0; i < 4; i++) {
        int idx = tid + i * 128;
        float o = (v[i] - mean) * invs * g[idx] + bet[idx];
        if (relu) o = fmaxf(o, 0.f);
        orow[idx] = o;
    }
}

// ---------------- host orchestration ----------------
static inline void gemm(const float* A, const float* Bm, const float* bias,
                        float* C, int M, int N, int K, int relu, int rnd) {
    dim3 grid((N + 127) / 128, M / 128);
    sgemm_kernel<<<grid, 256>>>(A, Bm, bias, C, M, N, K, relu, rnd);
}

extern "C" void kernel_launch(void* const* d_in, const int* in_sizes, int n_in,
                              void* d_out, int out_size) {
    const int*   src_ids  = (const int*)  d_in[0];
    const int*   tgt_ids  = (const int*)  d_in[1];
    const float* src_emb  = (const float*)d_in[2];
    const float* tgt_emb  = (const float*)d_in[3];
    const float* enc_wk   = (const float*)d_in[4];
    const float* enc_wv   = (const float*)d_in[5];
    const float* enc_wq   = (const float*)d_in[6];
    const float* enc_dw   = (const float*)d_in[7];
    const float* enc_db   = (const float*)d_in[8];
    const float* enc_ffw  = (const float*)d_in[9];
    const float* enc_ffb  = (const float*)d_in[10];
    const float* enc_ln_g = (const float*)d_in[11];
    const float* enc_ln_b = (const float*)d_in[12];
    const float* dec_swk  = (const float*)d_in[13];
    const float* dec_swv  = (const float*)d_in[14];
    const float* dec_swq  = (const float*)d_in[15];
    const float* dec_sdw  = (const float*)d_in[16];
    const float* dec_sdb  = (const float*)d_in[17];
    const float* dec_cwk  = (const float*)d_in[18];
    const float* dec_cwv  = (const float*)d_in[19];
    const float* dec_cwq  = (const float*)d_in[20];
    const float* dec_cdw  = (const float*)d_in[21];
    const float* dec_cdb  = (const float*)d_in[22];
    const float* dec_ffw  = (const float*)d_in[23];
    const float* dec_ffb  = (const float*)d_in[24];
    const float* dec_ln_g = (const float*)d_in[25];
    const float* dec_ln_b = (const float*)d_in[26];
    const float* cls_w1   = (const float*)d_in[27];
    const float* cls_b1   = (const float*)d_in[28];
    const float* cls_w2   = (const float*)d_in[29];
    const float* cls_b2   = (const float*)d_in[30];
    float* out = (float*)d_out;

    float *px, *py, *pq, *pk, *pv, *pat, *pt, *ph, *penc, *ph1, *ph2, *pdec, *pwp, *phid, *pw2r;
    cudaGetSymbolAddress((void**)&px,   g_x);
    cudaGetSymbolAddress((void**)&py,   g_y);
    cudaGetSymbolAddress((void**)&pq,   g_q);
    cudaGetSymbolAddress((void**)&pk,   g_k);
    cudaGetSymbolAddress((void**)&pv,   g_v);
    cudaGetSymbolAddress((void**)&pat,  g_att);
    cudaGetSymbolAddress((void**)&pt,   g_t);
    cudaGetSymbolAddress((void**)&ph,   g_h);
    cudaGetSymbolAddress((void**)&penc, g_enc);
    cudaGetSymbolAddress((void**)&ph1,  g_h1);
    cudaGetSymbolAddress((void**)&ph2,  g_h2);
    cudaGetSymbolAddress((void**)&pdec, g_dec);
    cudaGetSymbolAddress((void**)&pwp,  g_wp);
    cudaGetSymbolAddress((void**)&phid, g_hid);
    cudaGetSymbolAddress((void**)&pw2r, g_w2r);

    cudaFuncSetAttribute(tf32gemm_kernel,
                         cudaFuncAttributeMaxDynamicSharedMemorySize, 69632);

    const int WSZ = E_ * E_;
    repack_kernel<<<512, 512>>>(enc_wq,  pwp + 0 * WSZ);
    repack_kernel<<<512, 512>>>(enc_wk,  pwp + 1 * WSZ);
    repack_kernel<<<512, 512>>>(enc_wv,  pwp + 2 * WSZ);
    repack_kernel<<<512, 512>>>(dec_swq, pwp + 3 * WSZ);
    repack_kernel<<<512, 512>>>(dec_swk, pwp + 4 * WSZ);
    repack_kernel<<<512, 512>>>(dec_swv, pwp + 5 * WSZ);
    repack_kernel<<<512, 512>>>(dec_cwq, pwp + 6 * WSZ);
    repack_kernel<<<512, 512>>>(dec_cwk, pwp + 7 * WSZ);
    repack_kernel<<<512, 512>>>(dec_cwv, pwp + 8 * WSZ);

    // pre-round classifier-2 weights to tf32 (overlaps with the rest of the net)
    round_kernel<<<2048, 256>>>((const float4*)cls_w2, (float4*)pw2r,
                                (int)(((size_t)V1_ * V2_) / 4));

    embed_kernel<<<dim3(S_, B_), 128>>>(src_ids, src_emb, px);
    embed_kernel<<<dim3(S_, B_), 128>>>(tgt_ids, tgt_emb, py);

    dim3 agrid(512, 64);

    // ----- encoder -----
    gemm(px, pwp + 0 * WSZ, nullptr, pq, BS_, 512, 512, 0, 0);
    gemm(px, pwp + 1 * WSZ, nullptr, pk, BS_, 512, 512, 0, 0);
    gemm(px, pwp + 2 * WSZ, nullptr, pv, BS_, 512, 512, 0, 0);
    attn_kernel<<<agrid, 128>>>(pq, pk, pv, pat, 1);
    gemm(pat, enc_dw, enc_db, pt, BS_, 512, 512, 0, 0);
    ln_kernel<<<BS_, 128>>>(px, pt, enc_ln_g, enc_ln_b, ph, 0);
    gemm(ph, enc_ffw, enc_ffb, pt, BS_, 512, 512, 0, 0);
    ln_kernel<<<BS_, 128>>>(ph, pt, enc_ln_g, enc_ln_b, penc, 0);

    // ----- decoder self-attention -----
    gemm(py, pwp + 3 * WSZ, nullptr, pq, BS_, 512, 512, 0, 0);
    gemm(py, pwp + 4 * WSZ, nullptr, pk, BS_, 512, 512, 0, 0);
    gemm(py, pwp + 5 * WSZ, nullptr, pv, BS_, 512, 512, 0, 0);
    attn_kernel<<<agrid, 128>>>(pq, pk, pv, pat, 1);
    gemm(pat, dec_sdw, dec_sdb, pt, BS_, 512, 512, 0, 0);
    ln_kernel<<<BS_, 128>>>(py, pt, dec_ln_g, dec_ln_b, ph1, 0);

    // ----- decoder cross-attention -----
    gemm(ph1,  pwp + 6 * WSZ, nullptr, pq, BS_, 512, 512, 0, 0);
    gemm(penc, pwp + 7 * WSZ, nullptr, pk, BS_, 512, 512, 0, 0);
    gemm(penc, pwp + 8 * WSZ, nullptr, pv, BS_, 512, 512, 0, 0);
    attn_kernel<<<agrid, 128>>>(pq, pk, pv, pat, 0);
    gemm(pat, dec_cdw, dec_cdb, pt, BS_, 512, 512, 0, 0);
    ln_kernel<<<BS_, 128>>>(ph1, pt, dec_ln_g, dec_ln_b, ph2, 0);

    // ----- decoder FF + final LN(relu) -----
    gemm(ph2, dec_ffw, dec_ffb, pt, BS_, 512, 512, 0, 0);
    ln_kernel<<<BS_, 128>>>(ph2, pt, dec_ln_g, dec_ln_b, pdec, 1);

    // ----- classifier -----
    // cls1 in fp32 (accuracy headroom); epilogue relu + tf32-round of hidden
    gemm(pdec, cls_w1, cls_b1, phid, BS_, V1_, 512, 1, 1);
    // cls2: dominant GEMM on tensor cores (tf32)
    {
        dim3 g2((V2_ + 127) / 128, BS_ / 128);
        tf32gemm_kernel<<<g2, 256, 69632>>>(phid, pw2r, cls_b2, out, BS_, V2_, V1_);
    }
}

// round 8
// speedup vs baseline: 2.4989x; 1.6101x over previous
#include <cuda_runtime.h>
#include <cuda_fp16.h>
#include <math.h>
#include <stdint.h>

#define B_   8
#define S_   512
#define E_   512
#define BS_  4096            // B_*S_
#define TOK_ 2097152         // BS_*E_
#define V1_  16000
#define V2_  8000

// ---------------- scratch (device globals: allocation-free) ----------------
__device__ float g_x[TOK_];
__device__ float g_y[TOK_];
__device__ float g_q[TOK_];
__device__ float g_k[TOK_];
__device__ float g_v[TOK_];
__device__ float g_att[TOK_];
__device__ float g_t[TOK_];
__device__ float g_h[TOK_];
__device__ float g_enc[TOK_];
__device__ float g_h1[TOK_];
__device__ float g_h2[TOK_];
__device__ float g_dec[TOK_];
__device__ float g_wp[9 * E_ * E_];                       // repacked attn weights
__device__ __align__(16) __half g_dh[BS_ * E_];           // dec_out hi
__device__ __align__(16) __half g_dl[BS_ * E_];           // dec_out lo
__device__ __align__(16) __half g_w1h[(size_t)V1_ * E_];  // w1^T hi [16000,512]
__device__ __align__(16) __half g_w1l[(size_t)V1_ * E_];
__device__ __align__(16) __half g_ah[(size_t)BS_ * V1_];  // hidden hi [4096,16000]
__device__ __align__(16) __half g_al[(size_t)BS_ * V1_];
__device__ __align__(16) __half g_w2h[(size_t)V2_ * V1_]; // w2^T hi [8000,16000]
__device__ __align__(16) __half g_w2l[(size_t)V2_ * V1_];

// ---------------- helpers ----------------
__device__ __forceinline__ void cp16(uint32_t dst, const void* src, int sbytes) {
    asm volatile("cp.async.cg.shared.global [%0], [%1], 16, %2;\n"
                 :: "r"(dst), "l"(src), "r"(sbytes));
}
// swizzled offset inside one 128x32(fp16) tile: pairs of 64B rows share a 128B line,
// 16B chunks XOR-swizzled so ldmatrix phases are bank-conflict-free.
__device__ __forceinline__ uint32_t swz(int r, int c) {
    return (uint32_t)(((r >> 1) << 7) + (((((r & 1) << 2) | c) ^ ((r >> 1) & 7)) << 4));
}
#define LDMX4(R, A)                                                            \
    asm volatile("ldmatrix.sync.aligned.m8n8.x4.shared.b16 {%0,%1,%2,%3}, [%4];" \
                 : "=r"((R)[0]), "=r"((R)[1]), "=r"((R)[2]), "=r"((R)[3]) : "r"(A))
#define MMA16816(D, A, B0, B1)                                                 \
    asm volatile("mma.sync.aligned.m16n8k16.row.col.f32.f16.f16.f32 "          \
                 "{%0,%1,%2,%3}, {%4,%5,%6,%7}, {%8,%9}, {%0,%1,%2,%3};"       \
                 : "+f"((D)[0]), "+f"((D)[1]), "+f"((D)[2]), "+f"((D)[3])      \
                 : "r"((A)[0]), "r"((A)[1]), "r"((A)[2]), "r"((A)[3]),         \
                   "r"(B0), "r"(B1))

// ---------------- weight repack: [H][E][HD] -> [E][H*HD] ----------------
__global__ void repack_kernel(const float* __restrict__ w, float* __restrict__ wp) {
    int o = blockIdx.x * blockDim.x + threadIdx.x;
    int c = o & 511;
    int e = o >> 9;
    int h = c >> 6, d = c & 63;
    wp[o] = w[((h << 9) + e) * 64 + d];
}

// ---------------- fp16 hi/lo split (row-major) ----------------
__global__ void split_kernel(const float* __restrict__ in,
                             __half* __restrict__ oh,
                             __half* __restrict__ ol, int n) {
    int i = blockIdx.x * blockDim.x + threadIdx.x;
    int stride = gridDim.x * blockDim.x;
    for (; i < n; i += stride) {
        float v = in[i];
        __half h = __float2half_rn(v);
        oh[i] = h;
        ol[i] = __float2half_rn(v - __half2float(h));
    }
}

// ---------------- transpose + split: fp32 [K,N] -> fp16 [N,K] hi/lo ----------------
__global__ void __launch_bounds__(256) tsplit_kernel(
    const float* __restrict__ in, __half* __restrict__ oh,
    __half* __restrict__ ol, int K, int N)
{
    __shared__ float tile[32][33];
    const int tx = threadIdx.x & 31, ty = threadIdx.x >> 5;   // 32x8
    const int nb = blockIdx.x << 5, kb = blockIdx.y << 5;
    #pragma unroll
    for (int i = 0; i < 4; i++) {
        int k = kb + ty + i * 8;
        tile[ty + i * 8][tx] = in[(size_t)k * N + nb + tx];
    }
    __syncthreads();
    #pragma unroll
    for (int i = 0; i < 4; i++) {
        int n = nb + ty + i * 8;
        int k = kb + tx;
        float v = tile[tx][ty + i * 8];
        __half h = __float2half_rn(v);
        oh[(size_t)n * K + k] = h;
        ol[(size_t)n * K + k] = __float2half_rn(v - __half2float(h));
    }
}

// ---------------- embedding + positional encoding ----------------
__global__ void embed_kernel(const int* __restrict__ ids, const float* __restrict__ emb,
                             float* __restrict__ out) {
    int s = blockIdx.x, b = blockIdx.y;
    int id = ids[b * S_ + s];
    const float* er = emb + (size_t)id * E_;
    float* orow = out + ((size_t)b * S_ + s) * E_;
    const float scale = 22.627416997969522f;   // sqrt(512)
    for (int i = threadIdx.x; i < E_; i += blockDim.x) {
        int d = (i < 256) ? i : (i - 256);
        float rate = expf((float)d * (-9.210340371976184f / 256.f));
        float ang = (float)s * rate;
        float p = (i < 256) ? sinf(ang) : cosf(ang);
        orow[i] = er[i] * scale + p;
    }
}

// ---------------- fp32 SGEMM (14 small GEMMs) ----------------
__global__ void __launch_bounds__(256) sgemm_kernel(
    const float* __restrict__ A, const float* __restrict__ Bm,
    const float* __restrict__ bias, float* __restrict__ C,
    int M, int N, int K)
{
    __shared__ float As[8][128];
    __shared__ float Bs[8][128];
    const int tid  = threadIdx.x;
    const int row0 = blockIdx.y * 128;
    const int col0 = blockIdx.x * 128;

    const int arow = tid >> 1;
    const int acol = (tid & 1) << 2;
    const int brow = tid >> 5;
    const int bcol = (tid & 31) << 2;
    const int tx = tid & 15;
    const int ty = tid >> 4;

    const float* Aptr = A + (size_t)(row0 + arow) * K + acol;
    const float* Bptr = Bm + (size_t)brow * N + col0 + bcol;

    float acc[8][8];
    #pragma unroll
    for (int i = 0; i < 8; i++)
        #pragma unroll
        for (int j = 0; j < 8; j++) acc[i][j] = 0.f;

    for (int k0 = 0; k0 < K; k0 += 8) {
        float4 av = *(const float4*)Aptr;
        float4 bv = *(const float4*)Bptr;
        As[acol    ][arow] = av.x;
        As[acol + 1][arow] = av.y;
        As[acol + 2][arow] = av.z;
        As[acol + 3][arow] = av.w;
        *(float4*)&Bs[brow][bcol] = bv;
        __syncthreads();
        #pragma unroll
        for (int kk = 0; kk < 8; kk++) {
            float4 a0 = *(const float4*)&As[kk][ty * 8];
            float4 a1 = *(const float4*)&As[kk][ty * 8 + 4];
            float4 b0 = *(const float4*)&Bs[kk][tx * 8];
            float4 b1 = *(const float4*)&Bs[kk][tx * 8 + 4];
            float ar[8] = {a0.x, a0.y, a0.z, a0.w, a1.x, a1.y, a1.z, a1.w};
            float br[8] = {b0.x, b0.y, b0.z, b0.w, b1.x, b1.y, b1.z, b1.w};
            #pragma unroll
            for (int i = 0; i < 8; i++)
                #pragma unroll
                for (int j = 0; j < 8; j++)
                    acc[i][j] = fmaf(ar[i], br[j], acc[i][j]);
        }
        __syncthreads();
        Aptr += 8;
        Bptr += (size_t)8 * N;
    }

    #pragma unroll
    for (int i = 0; i < 8; i++) {
        int r = row0 + ty * 8 + i;
        float* Crow = C + (size_t)r * N;
        #pragma unroll
        for (int j = 0; j < 8; j += 4) {
            int c = col0 + tx * 8 + j;
            float4 v = make_float4(acc[i][j], acc[i][j+1], acc[i][j+2], acc[i][j+3]);
            if (bias) {
                v.x += bias[c];   v.y += bias[c+1];
                v.z += bias[c+2]; v.w += bias[c+3];
            }
            *(float4*)&Crow[c] = v;
        }
    }
}

// ---------------- fp16 hi/lo split HMMA GEMM (classifier) ----------------
// C = (Ah+Al)[M,K] @ (Bh+Bl)[N,K]^T, 3 terms (hh+hl+lh), fp32 accum.
// 128x128 tile, K stages of 32, 3-stage cp.async ring, ldmatrix fragments.
// mode 0: Cf = acc + bias.  mode 1: relu(acc+bias) -> split fp16 Ch/Cl.
__global__ void __launch_bounds__(256, 2) hgemm_kernel(
    const __half* __restrict__ Ah, const __half* __restrict__ Al,
    const __half* __restrict__ Bh, const __half* __restrict__ Bl,
    const float* __restrict__ bias, float* __restrict__ Cf,
    __half* __restrict__ Ch, __half* __restrict__ Cl,
    int NT, int N, int K, int mode)
{
    extern __shared__ char smem[];
    const uint32_t sb = (uint32_t)__cvta_generic_to_shared(smem);
    const int tid = threadIdx.x;
    const int lane = tid & 31, wid = tid >> 5;
    const int wm = wid >> 2, wn = wid & 3;             // 2x4 warps, 64x32 each

    // rasterize: groups of 8 N-tiles x 32 M-tiles (only last group may be partial)
    const int cg = blockIdx.x >> 8;
    const int rem = blockIdx.x & 255;
    const int w = min(8, NT - (cg << 3));
    const int nt = (cg << 3) + rem % w;
    const int mt = rem / w;
    const int row0 = mt << 7, col0 = nt << 7;

    float acc[4][4][4];
    #pragma unroll
    for (int a = 0; a < 4; a++)
        #pragma unroll
        for (int b = 0; b < 4; b++)
            #pragma unroll
            for (int c = 0; c < 4; c++) acc[a][b][c] = 0.f;

    const int nst = K >> 5;

    // stage slot S holds 4 tiles of 8KB: Ah, Al, Bh, Bl (128 rows x 32 fp16)
    #define FILL(T, S)                                                               \
    do {                                                                             \
        _Pragma("unroll")                                                            \
        for (int i = 0; i < 8; i++) {                                                \
            int cid = i * 256 + tid;                                                 \
            int tile = cid >> 9;                                                     \
            int w512 = cid & 511;                                                    \
            int r = w512 >> 2, c = w512 & 3;                                         \
            uint32_t dst = sb + (S) * 32768u + tile * 8192u + swz(r, c);             \
            const __half* src;                                                       \
            int pb = 16;                                                             \
            if (tile < 2) {                                                          \
                const __half* base = tile ? Al : Ah;                                 \
                src = base + (size_t)(row0 + r) * K + (T) * 32 + c * 8;              \
            } else {                                                                 \
                const __half* base = (tile == 2) ? Bh : Bl;                          \
                int n = col0 + r;                                                    \
                if (n < N) src = base + (size_t)n * K + (T) * 32 + c * 8;            \
                else { src = base; pb = 0; }                                         \
            }                                                                        \
            cp16(dst, src, pb);                                                      \
        }                                                                            \
        asm volatile("cp.async.commit_group;\n" ::);                                 \
    } while (0)

    FILL(0, 0);
    FILL(1, 1);

    // per-thread ldmatrix row/chunk geometry
    const int rA = wm * 64 + (lane & 15);          // + mf*16
    const int cA = (lane >> 4);                    // + 2*ks
    const int rB = wn * 32 + (lane & 7) + ((lane & 16) >> 1);   // + nf8*16
    const int cB = (lane >> 3) & 1;                // + 2*ks

    for (int t = 0; t < nst; ++t) {
        const int s = t % 3;
        if (t + 2 < nst) {
            FILL(t + 2, (t + 2) % 3);
            asm volatile("cp.async.wait_group 2;\n" ::);
        } else {
            asm volatile("cp.async.wait_group 0;\n" ::);
        }
        __syncthreads();

        const uint32_t tb = sb + s * 32768u;       // Ah | +8192 Al | +16384 Bh | +24576 Bl
        #pragma unroll
        for (int ks = 0; ks < 2; ks++) {
            uint32_t bh[2][4], bl[2][4], a[4][4];
            #pragma unroll
            for (int nf8 = 0; nf8 < 2; nf8++) {
                uint32_t off = swz(rB + nf8 * 16, 2 * ks + cB);
                LDMX4(bh[nf8], tb + 16384u + off);
                LDMX4(bl[nf8], tb + 24576u + off);
            }
            #pragma unroll
            for (int mf = 0; mf < 4; mf++) {
                LDMX4(a[mf], tb + swz(rA + mf * 16, 2 * ks + cA));
            }
            #pragma unroll
            for (int mf = 0; mf < 4; mf++)
                #pragma unroll
                for (int nf8 = 0; nf8 < 2; nf8++) {
                    MMA16816(acc[mf][nf8 * 2],     a[mf], bh[nf8][0], bh[nf8][1]);
                    MMA16816(acc[mf][nf8 * 2 + 1], a[mf], bh[nf8][2], bh[nf8][3]);
                    MMA16816(acc[mf][nf8 * 2],     a[mf], bl[nf8][0], bl[nf8][1]);
                    MMA16816(acc[mf][nf8 * 2 + 1], a[mf], bl[nf8][2], bl[nf8][3]);
                }
            #pragma unroll
            for (int mf = 0; mf < 4; mf++) {
                LDMX4(a[mf], tb + 8192u + swz(rA + mf * 16, 2 * ks + cA));  // A lo
            }
            #pragma unroll
            for (int mf = 0; mf < 4; mf++)
                #pragma unroll
                for (int nf8 = 0; nf8 < 2; nf8++) {
                    MMA16816(acc[mf][nf8 * 2],     a[mf], bh[nf8][0], bh[nf8][1]);
                    MMA16816(acc[mf][nf8 * 2 + 1], a[mf], bh[nf8][2], bh[nf8][3]);
                }
        }
        __syncthreads();
    }
    #undef FILL

    // epilogue: standard m16n8 C fragment layout
    const int erow = lane >> 2, ecol = (lane & 3) * 2;
    #pragma unroll
    for (int mf = 0; mf < 4; mf++) {
        #pragma unroll
        for (int nf = 0; nf < 4; nf++) {
            int r = row0 + wm * 64 + mf * 16 + erow;
            int c = col0 + wn * 32 + nf * 8 + ecol;
            if (c < N) {
                float b0 = bias[c], b1 = bias[c + 1];
                float v00 = acc[mf][nf][0] + b0, v01 = acc[mf][nf][1] + b1;
                float v10 = acc[mf][nf][2] + b0, v11 = acc[mf][nf][3] + b1;
                if (mode == 0) {
                    float* p0 = Cf + (size_t)r * N + c;
                    float* p1 = Cf + (size_t)(r + 8) * N + c;
                    p0[0] = v00; p0[1] = v01;
                    p1[0] = v10; p1[1] = v11;
                } else {
                    v00 = fmaxf(v00, 0.f); v01 = fmaxf(v01, 0.f);
                    v10 = fmaxf(v10, 0.f); v11 = fmaxf(v11, 0.f);
                    __half h;
                    size_t o00 = (size_t)r * N + c, o10 = (size_t)(r + 8) * N + c;
                    h = __float2half_rn(v00); Ch[o00]     = h; Cl[o00]     = __float2half_rn(v00 - __half2float(h));
                    h = __float2half_rn(v01); Ch[o00 + 1] = h; Cl[o00 + 1] = __float2half_rn(v01 - __half2float(h));
                    h = __float2half_rn(v10); Ch[o10]     = h; Cl[o10]     = __float2half_rn(v10 - __half2float(h));
                    h = __float2half_rn(v11); Ch[o10 + 1] = h; Cl[o10 + 1] = __float2half_rn(v11 - __half2float(h));
                }
            }
        }
    }
}

// ---------------- fused attention: one block per (b,h,q) ----------------
__global__ void __launch_bounds__(128) attn_kernel(
    const float* __restrict__ Q, const float* __restrict__ K,
    const float* __restrict__ V, float* __restrict__ O, int causal)
{
    const int q = blockIdx.x;
    const int b = blockIdx.y >> 3;
    const int h = blockIdx.y & 7;
    const int tid = threadIdx.x;
    __shared__ float qs[64];
    __shared__ float w[512];
    __shared__ float smax[4], ssum[4];
    __shared__ float part[128];

    const size_t base = (size_t)b * 262144 + (size_t)h * 64;
    if (tid < 64) qs[tid] = Q[base + (size_t)q * 512 + tid];
    __syncthreads();

    const float scale = 0.044194173824159216f;   // 1/sqrt(512)
    const int kmax = causal ? q : 511;
    float lk[4];
    float lmax = -1e30f;
    #pragma unroll
    for (int i = 0; i < 4; i++) {
        int k = tid + i * 128;
        float val = -1e30f;
        if (k <= kmax) {
            const float* Kr = K + base + (size_t)k * 512;
            float acc = 0.f;
            #pragma unroll
            for (int d = 0; d < 64; d += 4) {
                float4 kv = *(const float4*)(Kr + d);
                acc = fmaf(qs[d],   kv.x, acc);
                acc = fmaf(qs[d+1], kv.y, acc);
                acc = fmaf(qs[d+2], kv.z, acc);
                acc = fmaf(qs[d+3], kv.w, acc);
            }
            val = acc * scale;
        }
        lk[i] = val;
        lmax = fmaxf(lmax, val);
    }
    const int lane = tid & 31, wrp = tid >> 5;
    #pragma unroll
    for (int o = 16; o; o >>= 1) lmax = fmaxf(lmax, __shfl_xor_sync(0xffffffffu, lmax, o));
    if (!lane) smax[wrp] = lmax;
    __syncthreads();
    const float gmax = fmaxf(fmaxf(smax[0], smax[1]), fmaxf(smax[2], smax[3]));

    float lsum = 0.f;
    #pragma unroll
    for (int i = 0; i < 4; i++) {
        int k = tid + i * 128;
        float e = (k <= kmax) ? __expf(lk[i] - gmax) : 0.f;
        w[k] = e;
        lsum += e;
    }
    #pragma unroll
    for (int o = 16; o; o >>= 1) lsum += __shfl_xor_sync(0xffffffffu, lsum, o);
    if (!lane) ssum[wrp] = lsum;
    __syncthreads();
    const float inv = 1.f / (ssum[0] + ssum[1] + ssum[2] + ssum[3]);

    const int d = tid & 63, hh = tid >> 6;
    const float* Vb = V + base + d;
    float acc = 0.f;
    const int klim = kmax + 1;
    for (int k = hh; k < klim; k += 2)
        acc = fmaf(w[k], Vb[(size_t)k * 512], acc);
    part[tid] = acc;
    __syncthreads();
    if (tid < 64)
        O[base + (size_t)q * 512 + tid] = (part[tid] + part[tid + 64]) * inv;
}

// ---------------- residual + layernorm (+optional relu) ----------------
__global__ void __launch_bounds__(128) ln_kernel(
    const float* __restrict__ X, const float* __restrict__ R,
    const float* __restrict__ g, const float* __restrict__ bet,
    float* __restrict__ O, int relu)
{
    const int row = blockIdx.x;
    const float* xr = X + (size_t)row * 512;
    const float* rr = R + (size_t)row * 512;
    float* orow = O + (size_t)row * 512;
    const int tid = threadIdx.x;
    float v[4];
    float s = 0.f, sq = 0.f;
    #pragma unroll
    for (int i = 0; i < 4; i++) {
        int idx = tid + i * 128;
        float t = xr[idx] + rr[idx];
        v[i] = t; s += t; sq = fmaf(t, t, sq);
    }
    __shared__ float ss[4], sqs[4];
    #pragma unroll
    for (int o = 16; o; o >>= 1) {
        s  += __shfl_xor_sync(0xffffffffu, s, o);
        sq += __shfl_xor_sync(0xffffffffu, sq, o);
    }
    const int lane = tid & 31, wrp = tid >> 5;
    if (!lane) { ss[wrp] = s; sqs[wrp] = sq; }
    __syncthreads();
    s  = ss[0] + ss[1] + ss[2] + ss[3];
    sq = sqs[0] + sqs[1] + sqs[2] + sqs[3];
    const float mean = s * (1.f / 512.f);
    const float var = sq * (1.f / 512.f) - mean * mean;
    const float invs = rsqrtf(var + 1e-3f);
    #pragma unroll
    for (int i = 0; i < 4; i++) {
        int idx = tid + i * 128;
        float o = (v[i] - mean) * invs * g[idx] + bet[idx];
        if (relu) o = fmaxf(o, 0.f);
        orow[idx] = o;
    }
}

// ---------------- host orchestration ----------------
static inline void gemm(const float* A, const float* Bm, const float* bias,
                        float* C, int M, int N, int K) {
    dim3 grid(N / 128, M / 128);
    sgemm_kernel<<<grid, 256>>>(A, Bm, bias, C, M, N, K);
}

extern "C" void kernel_launch(void* const* d_in, const int* in_sizes, int n_in,
                              void* d_out, int out_size) {
    const int*   src_ids  = (const int*)  d_in[0];
    const int*   tgt_ids  = (const int*)  d_in[1];
    const float* src_emb  = (const float*)d_in[2];
    const float* tgt_emb  = (const float*)d_in[3];
    const float* enc_wk   = (const float*)d_in[4];
    const float* enc_wv   = (const float*)d_in[5];
    const float* enc_wq   = (const float*)d_in[6];
    const float* enc_dw   = (const float*)d_in[7];
    const float* enc_db   = (const float*)d_in[8];
    const float* enc_ffw  = (const float*)d_in[9];
    const float* enc_ffb  = (const float*)d_in[10];
    const float* enc_ln_g = (const float*)d_in[11];
    const float* enc_ln_b = (const float*)d_in[12];
    const float* dec_swk  = (const float*)d_in[13];
    const float* dec_swv  = (const float*)d_in[14];
    const float* dec_swq  = (const float*)d_in[15];
    const float* dec_sdw  = (const float*)d_in[16];
    const float* dec_sdb  = (const float*)d_in[17];
    const float* dec_cwk  = (const float*)d_in[18];
    const float* dec_cwv  = (const float*)d_in[19];
    const float* dec_cwq  = (const float*)d_in[20];
    const float* dec_cdw  = (const float*)d_in[21];
    const float* dec_cdb  = (const float*)d_in[22];
    const float* dec_ffw  = (const float*)d_in[23];
    const float* dec_ffb  = (const float*)d_in[24];
    const float* dec_ln_g = (const float*)d_in[25];
    const float* dec_ln_b = (const float*)d_in[26];
    const float* cls_w1   = (const float*)d_in[27];
    const float* cls_b1   = (const float*)d_in[28];
    const float* cls_w2   = (const float*)d_in[29];
    const float* cls_b2   = (const float*)d_in[30];
    float* out = (float*)d_out;

    float *px, *py, *pq, *pk, *pv, *pat, *pt, *ph, *penc, *ph1, *ph2, *pdec, *pwp;
    __half *pdh, *pdl, *pw1h, *pw1l, *pah, *pal, *pw2h, *pw2l;
    cudaGetSymbolAddress((void**)&px,   g_x);
    cudaGetSymbolAddress((void**)&py,   g_y);
    cudaGetSymbolAddress((void**)&pq,   g_q);
    cudaGetSymbolAddress((void**)&pk,   g_k);
    cudaGetSymbolAddress((void**)&pv,   g_v);
    cudaGetSymbolAddress((void**)&pat,  g_att);
    cudaGetSymbolAddress((void**)&pt,   g_t);
    cudaGetSymbolAddress((void**)&ph,   g_h);
    cudaGetSymbolAddress((void**)&penc, g_enc);
    cudaGetSymbolAddress((void**)&ph1,  g_h1);
    cudaGetSymbolAddress((void**)&ph2,  g_h2);
    cudaGetSymbolAddress((void**)&pdec, g_dec);
    cudaGetSymbolAddress((void**)&pwp,  g_wp);
    cudaGetSymbolAddress((void**)&pdh,  g_dh);
    cudaGetSymbolAddress((void**)&pdl,  g_dl);
    cudaGetSymbolAddress((void**)&pw1h, g_w1h);
    cudaGetSymbolAddress((void**)&pw1l, g_w1l);
    cudaGetSymbolAddress((void**)&pah,  g_ah);
    cudaGetSymbolAddress((void**)&pal,  g_al);
    cudaGetSymbolAddress((void**)&pw2h, g_w2h);
    cudaGetSymbolAddress((void**)&pw2l, g_w2l);

    cudaFuncSetAttribute(hgemm_kernel,
                         cudaFuncAttributeMaxDynamicSharedMemorySize, 98304);

    const int WSZ = E_ * E_;
    repack_kernel<<<512, 512>>>(enc_wq,  pwp + 0 * WSZ);
    repack_kernel<<<512, 512>>>(enc_wk,  pwp + 1 * WSZ);
    repack_kernel<<<512, 512>>>(enc_wv,  pwp + 2 * WSZ);
    repack_kernel<<<512, 512>>>(dec_swq, pwp + 3 * WSZ);
    repack_kernel<<<512, 512>>>(dec_swk, pwp + 4 * WSZ);
    repack_kernel<<<512, 512>>>(dec_swv, pwp + 5 * WSZ);
    repack_kernel<<<512, 512>>>(dec_cwq, pwp + 6 * WSZ);
    repack_kernel<<<512, 512>>>(dec_cwk, pwp + 7 * WSZ);
    repack_kernel<<<512, 512>>>(dec_cwv, pwp + 8 * WSZ);

    // transpose+split classifier weights to K-major fp16 hi/lo
    tsplit_kernel<<<dim3(V1_ / 32, E_ / 32), 256>>>(cls_w1, pw1h, pw1l, E_, V1_);
    tsplit_kernel<<<dim3(V2_ / 32, V1_ / 32), 256>>>(cls_w2, pw2h, pw2l, V1_, V2_);

    embed_kernel<<<dim3(S_, B_), 128>>>(src_ids, src_emb, px);
    embed_kernel<<<dim3(S_, B_), 128>>>(tgt_ids, tgt_emb, py);

    dim3 agrid(512, 64);

    // ----- encoder -----
    gemm(px, pwp + 0 * WSZ, nullptr, pq, BS_, 512, 512);
    gemm(px, pwp + 1 * WSZ, nullptr, pk, BS_, 512, 512);
    gemm(px, pwp + 2 * WSZ, nullptr, pv, BS_, 512, 512);
    attn_kernel<<<agrid, 128>>>(pq, pk, pv, pat, 1);
    gemm(pat, enc_dw, enc_db, pt, BS_, 512, 512);
    ln_kernel<<<BS_, 128>>>(px, pt, enc_ln_g, enc_ln_b, ph, 0);
    gemm(ph, enc_ffw, enc_ffb, pt, BS_, 512, 512);
    ln_kernel<<<BS_, 128>>>(ph, pt, enc_ln_g, enc_ln_b, penc, 0);

    // ----- decoder self-attention -----
    gemm(py, pwp + 3 * WSZ, nullptr, pq, BS_, 512, 512);
    gemm(py, pwp + 4 * WSZ, nullptr, pk, BS_, 512, 512);
    gemm(py, pwp + 5 * WSZ, nullptr, pv, BS_, 512, 512);
    attn_kernel<<<agrid, 128>>>(pq, pk, pv, pat, 1);
    gemm(pat, dec_sdw, dec_sdb, pt, BS_, 512, 512);
    ln_kernel<<<BS_, 128>>>(py, pt, dec_ln_g, dec_ln_b, ph1, 0);

    // ----- decoder cross-attention -----
    gemm(ph1,  pwp + 6 * WSZ, nullptr, pq, BS_, 512, 512);
    gemm(penc, pwp + 7 * WSZ, nullptr, pk, BS_, 512, 512);
    gemm(penc, pwp + 8 * WSZ, nullptr, pv, BS_, 512, 512);
    attn_kernel<<<agrid, 128>>>(pq, pk, pv, pat, 0);
    gemm(pat, dec_cdw, dec_cdb, pt, BS_, 512, 512);
    ln_kernel<<<BS_, 128>>>(ph1, pt, dec_ln_g, dec_ln_b, ph2, 0);

    // ----- decoder FF + final LN(relu) -----
    gemm(ph2, dec_ffw, dec_ffb, pt, BS_, 512, 512);
    ln_kernel<<<BS_, 128>>>(ph2, pt, dec_ln_g, dec_ln_b, pdec, 1);

    // ----- classifier on fp16-split HMMA -----
    split_kernel<<<1024, 256>>>(pdec, pdh, pdl, BS_ * E_);
    // cls1: [4096,512] x [512,16000] -> relu + split fp16 hidden
    hgemm_kernel<<<(V1_ / 128) * 32, 256, 98304>>>(
        pdh, pdl, pw1h, pw1l, cls_b1, nullptr, pah, pal,
        V1_ / 128, V1_, E_, 1);
    // cls2: [4096,16000] x [16000,8000] -> fp32 out (N tail handled via pb/guards)
    hgemm_kernel<<<((V2_ + 127) / 128) * 32, 256, 98304>>>(
        pah, pal, pw2h, pw2l, cls_b2, out, nullptr, nullptr,
        (V2_ + 127) / 128, V2_, V1_, 0);
}

// round 13
// speedup vs baseline: 3.2465x; 1.2992x over previous
#include <cuda_runtime.h>
#include <cuda_fp16.h>
#include <math.h>
#include <stdint.h>

#define B_   8
#define S_   512
#define E_   512
#define BS_  4096            // B_*S_
#define TOK_ 2097152         // BS_*E_
#define V1_  16000
#define V2_  8000

// ---------------- scratch (device globals: allocation-free) ----------------
__device__ float g_x[TOK_];
__device__ float g_y[TOK_];
__device__ float g_q[TOK_];
__device__ float g_k[TOK_];
__device__ float g_v[TOK_];
__device__ float g_att[TOK_];
__device__ float g_t[TOK_];
__device__ float g_h[TOK_];
__device__ float g_enc[TOK_];
__device__ float g_h1[TOK_];
__device__ float g_h2[TOK_];
__device__ float g_dec[TOK_];
__device__ float g_wp[9 * E_ * E_];                       // repacked attn weights
__device__ __align__(16) __half g_dh[BS_ * E_];           // dec_out hi
__device__ __align__(16) __half g_dl[BS_ * E_];           // dec_out lo
__device__ __align__(16) __half g_w1h[(size_t)V1_ * E_];  // w1^T hi [16000,512]
__device__ __align__(16) __half g_w1l[(size_t)V1_ * E_];
__device__ __align__(16) __half g_ah[(size_t)BS_ * V1_];  // hidden hi [4096,16000]
__device__ __align__(16) __half g_w2h[(size_t)V2_ * V1_]; // w2^T hi [8000,16000]
__device__ __align__(16) __half g_w2l[(size_t)V2_ * V1_];

// ---------------- helpers ----------------
__device__ __forceinline__ void cp16(uint32_t dst, const void* src, int sbytes) {
    asm volatile("cp.async.cg.shared.global [%0], [%1], 16, %2;\n"
                 :: "r"(dst), "l"(src), "r"(sbytes));
}
// swizzled offset inside one 128x32(fp16) tile: pairs of 64B rows share a 128B line,
// 16B chunks XOR-swizzled so ldmatrix phases are bank-conflict-free.
__device__ __forceinline__ uint32_t swz(int r, int c) {
    return (uint32_t)(((r >> 1) << 7) + (((((r & 1) << 2) | c) ^ ((r >> 1) & 7)) << 4));
}
#define LDMX4(R, A)                                                            \
    asm volatile("ldmatrix.sync.aligned.m8n8.x4.shared.b16 {%0,%1,%2,%3}, [%4];" \
                 : "=r"((R)[0]), "=r"((R)[1]), "=r"((R)[2]), "=r"((R)[3]) : "r"(A))
#define MMA16816(D, A, B0, B1)                                                 \
    asm volatile("mma.sync.aligned.m16n8k16.row.col.f32.f16.f16.f32 "          \
                 "{%0,%1,%2,%3}, {%4,%5,%6,%7}, {%8,%9}, {%0,%1,%2,%3};"       \
                 : "+f"((D)[0]), "+f"((D)[1]), "+f"((D)[2]), "+f"((D)[3])      \
                 : "r"((A)[0]), "r"((A)[1]), "r"((A)[2]), "r"((A)[3]),         \
                   "r"(B0), "r"(B1))

// ---------------- merged weight repack: 9x [H][E][HD] -> [E][H*HD] ----------------
__global__ void repack9_kernel(
    const float* w0, const float* w1, const float* w2,
    const float* w3, const float* w4, const float* w5,
    const float* w6, const float* w7, const float* w8,
    float* __restrict__ wp)
{
    const float* w;
    switch (blockIdx.y) {
        case 0: w = w0; break; case 1: w = w1; break; case 2: w = w2; break;
        case 3: w = w3; break; case 4: w = w4; break; case 5: w = w5; break;
        case 6: w = w6; break; case 7: w = w7; break; default: w = w8; break;
    }
    int o = blockIdx.x * blockDim.x + threadIdx.x;   // 0..262143
    int c = o & 511;
    int e = o >> 9;
    int h = c >> 6, d = c & 63;
    wp[(size_t)blockIdx.y * (E_ * E_) + o] = w[((h << 9) + e) * 64 + d];
}

// ---------------- fp16 hi/lo split (row-major) ----------------
__global__ void split_kernel(const float* __restrict__ in,
                             __half* __restrict__ oh,
                             __half* __restrict__ ol, int n) {
    int i = blockIdx.x * blockDim.x + threadIdx.x;
    int stride = gridDim.x * blockDim.x;
    for (; i < n; i += stride) {
        float v = in[i];
        __half h = __float2half_rn(v);
        oh[i] = h;
        ol[i] = __float2half_rn(v - __half2float(h));
    }
}

// ---------------- transpose + split: fp32 [K,N] -> fp16 [N,K] hi/lo ----------------
__global__ void __launch_bounds__(256) tsplit_kernel(
    const float* __restrict__ in, __half* __restrict__ oh,
    __half* __restrict__ ol, int K, int N)
{
    __shared__ float tile[32][33];
    const int tx = threadIdx.x & 31, ty = threadIdx.x >> 5;   // 32x8
    const int nb = blockIdx.x << 5, kb = blockIdx.y << 5;
    #pragma unroll
    for (int i = 0; i < 4; i++) {
        int k = kb + ty + i * 8;
        tile[ty + i * 8][tx] = in[(size_t)k * N + nb + tx];
    }
    __syncthreads();
    #pragma unroll
    for (int i = 0; i < 4; i++) {
        int n = nb + ty + i * 8;
        int k = kb + tx;
        float v = tile[tx][ty + i * 8];
        __half h = __float2half_rn(v);
        oh[(size_t)n * K + k] = h;
        ol[(size_t)n * K + k] = __float2half_rn(v - __half2float(h));
    }
}

// ---------------- embedding + positional encoding ----------------
__global__ void embed_kernel(const int* __restrict__ ids, const float* __restrict__ emb,
                             float* __restrict__ out) {
    int s = blockIdx.x, b = blockIdx.y;
    int id = ids[b * S_ + s];
    const float* er = emb + (size_t)id * E_;
    float* orow = out + ((size_t)b * S_ + s) * E_;
    const float scale = 22.627416997969522f;   // sqrt(512)
    for (int i = threadIdx.x; i < E_; i += blockDim.x) {
        int d = (i < 256) ? i : (i - 256);
        float rate = expf((float)d * (-9.210340371976184f / 256.f));
        float ang = (float)s * rate;
        float p = (i < 256) ? sinf(ang) : cosf(ang);
        orow[i] = er[i] * scale + p;
    }
}

// ---------------- fp32 SGEMM (14 small GEMMs) ----------------
__global__ void __launch_bounds__(256) sgemm_kernel(
    const float* __restrict__ A, const float* __restrict__ Bm,
    const float* __restrict__ bias, float* __restrict__ C,
    int M, int N, int K)
{
    __shared__ float As[8][128];
    __shared__ float Bs[8][128];
    const int tid  = threadIdx.x;
    const int row0 = blockIdx.y * 128;
    const int col0 = blockIdx.x * 128;

    const int arow = tid >> 1;
    const int acol = (tid & 1) << 2;
    const int brow = tid >> 5;
    const int bcol = (tid & 31) << 2;
    const int tx = tid & 15;
    const int ty = tid >> 4;

    const float* Aptr = A + (size_t)(row0 + arow) * K + acol;
    const float* Bptr = Bm + (size_t)brow * N + col0 + bcol;

    float acc[8][8];
    #pragma unroll
    for (int i = 0; i < 8; i++)
        #pragma unroll
        for (int j = 0; j < 8; j++) acc[i][j] = 0.f;

    for (int k0 = 0; k0 < K; k0 += 8) {
        float4 av = *(const float4*)Aptr;
        float4 bv = *(const float4*)Bptr;
        As[acol    ][arow] = av.x;
        As[acol + 1][arow] = av.y;
        As[acol + 2][arow] = av.z;
        As[acol + 3][arow] = av.w;
        *(float4*)&Bs[brow][bcol] = bv;
        __syncthreads();
        #pragma unroll
        for (int kk = 0; kk < 8; kk++) {
            float4 a0 = *(const float4*)&As[kk][ty * 8];
            float4 a1 = *(const float4*)&As[kk][ty * 8 + 4];
            float4 b0 = *(const float4*)&Bs[kk][tx * 8];
            float4 b1 = *(const float4*)&Bs[kk][tx * 8 + 4];
            float ar[8] = {a0.x, a0.y, a0.z, a0.w, a1.x, a1.y, a1.z, a1.w};
            float br[8] = {b0.x, b0.y, b0.z, b0.w, b1.x, b1.y, b1.z, b1.w};
            #pragma unroll
            for (int i = 0; i < 8; i++)
                #pragma unroll
                for (int j = 0; j < 8; j++)
                    acc[i][j] = fmaf(ar[i], br[j], acc[i][j]);
        }
        __syncthreads();
        Aptr += 8;
        Bptr += (size_t)8 * N;
    }

    #pragma unroll
    for (int i = 0; i < 8; i++) {
        int r = row0 + ty * 8 + i;
        float* Crow = C + (size_t)r * N;
        #pragma unroll
        for (int j = 0; j < 8; j += 4) {
            int c = col0 + tx * 8 + j;
            float4 v = make_float4(acc[i][j], acc[i][j+1], acc[i][j+2], acc[i][j+3]);
            if (bias) {
                v.x += bias[c];   v.y += bias[c+1];
                v.z += bias[c+2]; v.w += bias[c+3];
            }
            *(float4*)&Crow[c] = v;
        }
    }
}

// ================= fp16 split HMMA GEMM #1: 3-term (cls1) =================
// C = (Ah+Al)@(Bh+Bl)^T (hh+hl+lh). Tiles Ah,Al,Bh,Bl (32KB/stage); ring 3.
// Epilogue: Ch = fp16(relu(acc+bias)).
__global__ void __launch_bounds__(256, 2) hgemm3_kernel(
    const __half* __restrict__ Ah, const __half* __restrict__ Al,
    const __half* __restrict__ Bh, const __half* __restrict__ Bl,
    const float* __restrict__ bias, __half* __restrict__ Ch,
    int NT, int N, int K)
{
    extern __shared__ char smem[];
    const uint32_t sb = (uint32_t)__cvta_generic_to_shared(smem);
    const int tid = threadIdx.x;
    const int lane = tid & 31, wid = tid >> 5;
    const int wm = wid >> 2, wn = wid & 3;

    const int cg = blockIdx.x >> 8;
    const int rem = blockIdx.x & 255;
    const int w = min(8, NT - (cg << 3));
    const int nt = (cg << 3) + rem % w;
    const int mt = rem / w;
    const int row0 = mt << 7, col0 = nt << 7;

    float acc[4][4][4];
    #pragma unroll
    for (int a = 0; a < 4; a++)
        #pragma unroll
        for (int b = 0; b < 4; b++)
            #pragma unroll
            for (int c = 0; c < 4; c++) acc[a][b][c] = 0.f;

    const int nst = K >> 5;

    #define FILL3(T, S)                                                              \
    do {                                                                             \
        _Pragma("unroll")                                                            \
        for (int i = 0; i < 8; i++) {                                                \
            int cid = i * 256 + tid;                                                 \
            int tile = cid >> 9;                                                     \
            int w512 = cid & 511;                                                    \
            int r = w512 >> 2, c = w512 & 3;                                         \
            uint32_t dst = sb + (S) * 32768u + tile * 8192u + swz(r, c);             \
            const __half* src;                                                       \
            int pb = 16;                                                             \
            if (tile < 2) {                                                          \
                const __half* base = tile ? Al : Ah;                                 \
                src = base + (size_t)(row0 + r) * K + (T) * 32 + c * 8;              \
            } else {                                                                 \
                const __half* base = (tile == 2) ? Bh : Bl;                          \
                int n = col0 + r;                                                    \
                if (n < N) src = base + (size_t)n * K + (T) * 32 + c * 8;            \
                else { src = base; pb = 0; }                                         \
            }                                                                        \
            cp16(dst, src, pb);                                                      \
        }                                                                            \
        asm volatile("cp.async.commit_group;\n" ::);                                 \
    } while (0)

    FILL3(0, 0);
    FILL3(1, 1);

    const int rA = wm * 64 + (lane & 15);
    const int cA = (lane >> 4);
    const int rB = wn * 32 + (lane & 7) + ((lane & 16) >> 1);
    const int cB = (lane >> 3) & 1;

    for (int t = 0; t < nst; ++t) {
        const int s = t % 3;
        if (t + 2 < nst) {
            FILL3(t + 2, (t + 2) % 3);
            asm volatile("cp.async.wait_group 2;\n" ::);
        } else {
            asm volatile("cp.async.wait_group 0;\n" ::);
        }
        __syncthreads();

        const uint32_t tb = sb + s * 32768u;
        #pragma unroll
        for (int ks = 0; ks < 2; ks++) {
            uint32_t bh[2][4], bl[2][4], a[4][4];
            #pragma unroll
            for (int nf8 = 0; nf8 < 2; nf8++) {
                uint32_t off = swz(rB + nf8 * 16, 2 * ks + cB);
                LDMX4(bh[nf8], tb + 16384u + off);
                LDMX4(bl[nf8], tb + 24576u + off);
            }
            #pragma unroll
            for (int mf = 0; mf < 4; mf++) {
                LDMX4(a[mf], tb + swz(rA + mf * 16, 2 * ks + cA));
            }
            #pragma unroll
            for (int mf = 0; mf < 4; mf++)
                #pragma unroll
                for (int nf8 = 0; nf8 < 2; nf8++) {
                    MMA16816(acc[mf][nf8 * 2],     a[mf], bh[nf8][0], bh[nf8][1]);
                    MMA16816(acc[mf][nf8 * 2 + 1], a[mf], bh[nf8][2], bh[nf8][3]);
                    MMA16816(acc[mf][nf8 * 2],     a[mf], bl[nf8][0], bl[nf8][1]);
                    MMA16816(acc[mf][nf8 * 2 + 1], a[mf], bl[nf8][2], bl[nf8][3]);
                }
            #pragma unroll
            for (int mf = 0; mf < 4; mf++) {
                LDMX4(a[mf], tb + 8192u + swz(rA + mf * 16, 2 * ks + cA));   // A lo
            }
            #pragma unroll
            for (int mf = 0; mf < 4; mf++)
                #pragma unroll
                for (int nf8 = 0; nf8 < 2; nf8++) {
                    MMA16816(acc[mf][nf8 * 2],     a[mf], bh[nf8][0], bh[nf8][1]);
                    MMA16816(acc[mf][nf8 * 2 + 1], a[mf], bh[nf8][2], bh[nf8][3]);
                }
        }
        __syncthreads();
    }
    #undef FILL3

    const int erow = lane >> 2, ecol = (lane & 3) * 2;
    #pragma unroll
    for (int mf = 0; mf < 4; mf++) {
        #pragma unroll
        for (int nf = 0; nf < 4; nf++) {
            int r = row0 + wm * 64 + mf * 16 + erow;
            int c = col0 + wn * 32 + nf * 8 + ecol;
            if (c < N) {
                float b0 = bias[c], b1 = bias[c + 1];
                size_t o00 = (size_t)r * N + c, o10 = (size_t)(r + 8) * N + c;
                Ch[o00]     = __float2half_rn(fmaxf(acc[mf][nf][0] + b0, 0.f));
                Ch[o00 + 1] = __float2half_rn(fmaxf(acc[mf][nf][1] + b1, 0.f));
                Ch[o10]     = __float2half_rn(fmaxf(acc[mf][nf][2] + b0, 0.f));
                Ch[o10 + 1] = __float2half_rn(fmaxf(acc[mf][nf][3] + b1, 0.f));
            }
        }
    }
}

// ================= fp16 split HMMA GEMM #2: 2-term (cls2) =================
// C = Ah@(Bh+Bl)^T (hh+hl). Tiles Ah,Bh,Bl (24KB/stage); ring 4.
// Epilogue: Cf = acc + bias (fp32).
__global__ void __launch_bounds__(256, 2) hgemm2_kernel(
    const __half* __restrict__ Ah,
    const __half* __restrict__ Bh, const __half* __restrict__ Bl,
    const float* __restrict__ bias, float* __restrict__ Cf,
    int NT, int N, int K)
{
    extern __shared__ char smem[];
    const uint32_t sb = (uint32_t)__cvta_generic_to_shared(smem);
    const int tid = threadIdx.x;
    const int lane = tid & 31, wid = tid >> 5;
    const int wm = wid >> 2, wn = wid & 3;

    const int cg = blockIdx.x >> 8;
    const int rem = blockIdx.x & 255;
    const int w = min(8, NT - (cg << 3));
    const int nt = (cg << 3) + rem % w;
    const int mt = rem / w;
    const int row0 = mt << 7, col0 = nt << 7;

    float acc[4][4][4];
    #pragma unroll
    for (int a = 0; a < 4; a++)
        #pragma unroll
        for (int b = 0; b < 4; b++)
            #pragma unroll
            for (int c = 0; c < 4; c++) acc[a][b][c] = 0.f;

    const int nst = K >> 5;

    #define FILL2(T, S)                                                              \
    do {                                                                             \
        _Pragma("unroll")                                                            \
        for (int i = 0; i < 6; i++) {                                                \
            int cid = i * 256 + tid;                                                 \
            int tile = cid >> 9;                                                     \
            int w512 = cid & 511;                                                    \
            int r = w512 >> 2, c = w512 & 3;                                         \
            uint32_t dst = sb + (S) * 24576u + tile * 8192u + swz(r, c);             \
            const __half* src;                                                       \
            int pb = 16;                                                             \
            if (tile == 0) {                                                         \
                src = Ah + (size_t)(row0 + r) * K + (T) * 32 + c * 8;                \
            } else {                                                                 \
                const __half* base = (tile == 1) ? Bh : Bl;                          \
                int n = col0 + r;                                                    \
                if (n < N) src = base + (size_t)n * K + (T) * 32 + c * 8;            \
                else { src = base; pb = 0; }                                         \
            }                                                                        \
            cp16(dst, src, pb);                                                      \
        }                                                                            \
        asm volatile("cp.async.commit_group;\n" ::);                                 \
    } while (0)

    FILL2(0, 0);
    FILL2(1, 1);
    FILL2(2, 2);

    const int rA = wm * 64 + (lane & 15);
    const int cA = (lane >> 4);
    const int rB = wn * 32 + (lane & 7) + ((lane & 16) >> 1);
    const int cB = (lane >> 3) & 1;

    for (int t = 0; t < nst; ++t) {
        const int s = t & 3;
        if (t + 3 < nst) {
            FILL2(t + 3, (t + 3) & 3);
            asm volatile("cp.async.wait_group 3;\n" ::);
        } else {
            asm volatile("cp.async.wait_group 0;\n" ::);
        }
        __syncthreads();

        const uint32_t tb = sb + s * 24576u;        // Ah | +8192 Bh | +16384 Bl
        #pragma unroll
        for (int ks = 0; ks < 2; ks++) {
            uint32_t bh[2][4], bl[2][4], a[4][4];
            #pragma unroll
            for (int nf8 = 0; nf8 < 2; nf8++) {
                uint32_t off = swz(rB + nf8 * 16, 2 * ks + cB);
                LDMX4(bh[nf8], tb + 8192u + off);
                LDMX4(bl[nf8], tb + 16384u + off);
            }
            #pragma unroll
            for (int mf = 0; mf < 4; mf++) {
                LDMX4(a[mf], tb + swz(rA + mf * 16, 2 * ks + cA));
            }
            #pragma unroll
            for (int mf = 0; mf < 4; mf++)
                #pragma unroll
                for (int nf8 = 0; nf8 < 2; nf8++) {
                    MMA16816(acc[mf][nf8 * 2],     a[mf], bh[nf8][0], bh[nf8][1]);
                    MMA16816(acc[mf][nf8 * 2 + 1], a[mf], bh[nf8][2], bh[nf8][3]);
                    MMA16816(acc[mf][nf8 * 2],     a[mf], bl[nf8][0], bl[nf8][1]);
                    MMA16816(acc[mf][nf8 * 2 + 1], a[mf], bl[nf8][2], bl[nf8][3]);
                }
        }
        __syncthreads();
    }
    #undef FILL2

    const int erow = lane >> 2, ecol = (lane & 3) * 2;
    #pragma unroll
    for (int mf = 0; mf < 4; mf++) {
        #pragma unroll
        for (int nf = 0; nf < 4; nf++) {
            int r = row0 + wm * 64 + mf * 16 + erow;
            int c = col0 + wn * 32 + nf * 8 + ecol;
            if (c < N) {
                float b0 = bias[c], b1 = bias[c + 1];
                float* p0 = Cf + (size_t)r * N + c;
                float* p1 = Cf + (size_t)(r + 8) * N + c;
                p0[0] = acc[mf][nf][0] + b0;
                p0[1] = acc[mf][nf][1] + b1;
                p1[0] = acc[mf][nf][2] + b0;
                p1[1] = acc[mf][nf][3] + b1;
            }
        }
    }
}

// ---------------- fused attention: one block per (b,h,q) ----------------
__global__ void __launch_bounds__(128) attn_kernel(
    const float* __restrict__ Q, const float* __restrict__ K,
    const float* __restrict__ V, float* __restrict__ O, int causal)
{
    const int q = blockIdx.x;
    const int b = blockIdx.y >> 3;
    const int h = blockIdx.y & 7;
    const int tid = threadIdx.x;
    __shared__ float qs[64];
    __shared__ float w[512];
    __shared__ float smax[4], ssum[4];
    __shared__ float part[128];

    const size_t base = (size_t)b * 262144 + (size_t)h * 64;
    if (tid < 64) qs[tid] = Q[base + (size_t)q * 512 + tid];
    __syncthreads();

    const float scale = 0.044194173824159216f;   // 1/sqrt(512)
    const int kmax = causal ? q : 511;
    float lk[4];
    float lmax = -1e30f;
    #pragma unroll
    for (int i = 0; i < 4; i++) {
        int k = tid + i * 128;
        float val = -1e30f;
        if (k <= kmax) {
            const float* Kr = K + base + (size_t)k * 512;
            float acc = 0.f;
            #pragma unroll
            for (int d = 0; d < 64; d += 4) {
                float4 kv = *(const float4*)(Kr + d);
                acc = fmaf(qs[d],   kv.x, acc);
                acc = fmaf(qs[d+1], kv.y, acc);
                acc = fmaf(qs[d+2], kv.z, acc);
                acc = fmaf(qs[d+3], kv.w, acc);
            }
            val = acc * scale;
        }
        lk[i] = val;
        lmax = fmaxf(lmax, val);
    }
    const int lane = tid & 31, wrp = tid >> 5;
    #pragma unroll
    for (int o = 16; o; o >>= 1) lmax = fmaxf(lmax, __shfl_xor_sync(0xffffffffu, lmax, o));
    if (!lane) smax[wrp] = lmax;
    __syncthreads();
    const float gmax = fmaxf(fmaxf(smax[0], smax[1]), fmaxf(smax[2], smax[3]));

    float lsum = 0.f;
    #pragma unroll
    for (int i = 0; i < 4; i++) {
        int k = tid + i * 128;
        float e = (k <= kmax) ? __expf(lk[i] - gmax) : 0.f;
        w[k] = e;
        lsum += e;
    }
    #pragma unroll
    for (int o = 16; o; o >>= 1) lsum += __shfl_xor_sync(0xffffffffu, lsum, o);
    if (!lane) ssum[wrp] = lsum;
    __syncthreads();
    const float inv = 1.f / (ssum[0] + ssum[1] + ssum[2] + ssum[3]);

    const int d = tid & 63, hh = tid >> 6;
    const float* Vb = V + base + d;
    float acc = 0.f;
    const int klim = kmax + 1;
    for (int k = hh; k < klim; k += 2)
        acc = fmaf(w[k], Vb[(size_t)k * 512], acc);
    part[tid] = acc;
    __syncthreads();
    if (tid < 64)
        O[base + (size_t)q * 512 + tid] = (part[tid] + part[tid + 64]) * inv;
}

// ---------------- residual + layernorm (+optional relu) ----------------
__global__ void __launch_bounds__(128) ln_kernel(
    const float* __restrict__ X, const float* __restrict__ R,
    const float* __restrict__ g, const float* __restrict__ bet,
    float* __restrict__ O, int relu)
{
    const int row = blockIdx.x;
    const float* xr = X + (size_t)row * 512;
    const float* rr = R + (size_t)row * 512;
    float* orow = O + (size_t)row * 512;
    const int tid = threadIdx.x;
    float v[4];
    float s = 0.f, sq = 0.f;
    #pragma unroll
    for (int i = 0; i < 4; i++) {
        int idx = tid + i * 128;
        float t = xr[idx] + rr[idx];
        v[i] = t; s += t; sq = fmaf(t, t, sq);
    }
    __shared__ float ss[4], sqs[4];
    #pragma unroll
    for (int o = 16; o; o >>= 1) {
        s  += __shfl_xor_sync(0xffffffffu, s, o);
        sq += __shfl_xor_sync(0xffffffffu, sq, o);
    }
    const int lane = tid & 31, wrp = tid >> 5;
    if (!lane) { ss[wrp] = s; sqs[wrp] = sq; }
    __syncthreads();
    s  = ss[0] + ss[1] + ss[2] + ss[3];
    sq = sqs[0] + sqs[1] + sqs[2] + sqs[3];
    const float mean = s * (1.f / 512.f);
    const float var = sq * (1.f / 512.f) - mean * mean;
    const float invs = rsqrtf(var + 1e-3f);
    #pragma unroll
    for (int i = 0; i < 4; i++) {
        int idx = tid + i * 128;
        float o = (v[i] - mean) * invs * g[idx] + bet[idx];
        if (relu) o = fmaxf(o, 0.f);
        orow[idx] = o;
    }
}

// ---------------- host orchestration ----------------
static inline void gemm(const float* A, const float* Bm, const float* bias,
                        float* C, int M, int N, int K) {
    dim3 grid(N / 128, M / 128);
    sgemm_kernel<<<grid, 256>>>(A, Bm, bias, C, M, N, K);
}

extern "C" void kernel_launch(void* const* d_in, const int* in_sizes, int n_in,
                              void* d_out, int out_size) {
    const int*   src_ids  = (const int*)  d_in[0];
    const int*   tgt_ids  = (const int*)  d_in[1];
    const float* src_emb  = (const float*)d_in[2];
    const float* tgt_emb  = (const float*)d_in[3];
    const float* enc_wk   = (const float*)d_in[4];
    const float* enc_wv   = (const float*)d_in[5];
    const float* enc_wq   = (const float*)d_in[6];
    const float* enc_dw   = (const float*)d_in[7];
    const float* enc_db   = (const float*)d_in[8];
    const float* enc_ffw  = (const float*)d_in[9];
    const float* enc_ffb  = (const float*)d_in[10];
    const float* enc_ln_g = (const float*)d_in[11];
    const float* enc_ln_b = (const float*)d_in[12];
    const float* dec_swk  = (const float*)d_in[13];
    const float* dec_swv  = (const float*)d_in[14];
    const float* dec_swq  = (const float*)d_in[15];
    const float* dec_sdw  = (const float*)d_in[16];
    const float* dec_sdb  = (const float*)d_in[17];
    const float* dec_cwk  = (const float*)d_in[18];
    const float* dec_cwv  = (const float*)d_in[19];
    const float* dec_cwq  = (const float*)d_in[20];
    const float* dec_cdw  = (const float*)d_in[21];
    const float* dec_cdb  = (const float*)d_in[22];
    const float* dec_ffw  = (const float*)d_in[23];
    const float* dec_ffb  = (const float*)d_in[24];
    const float* dec_ln_g = (const float*)d_in[25];
    const float* dec_ln_b = (const float*)d_in[26];
    const float* cls_w1   = (const float*)d_in[27];
    const float* cls_b1   = (const float*)d_in[28];
    const float* cls_w2   = (const float*)d_in[29];
    const float* cls_b2   = (const float*)d_in[30];
    float* out = (float*)d_out;

    float *px, *py, *pq, *pk, *pv, *pat, *pt, *ph, *penc, *ph1, *ph2, *pdec, *pwp;
    __half *pdh, *pdl, *pw1h, *pw1l, *pah, *pw2h, *pw2l;
    cudaGetSymbolAddress((void**)&px,   g_x);
    cudaGetSymbolAddress((void**)&py,   g_y);
    cudaGetSymbolAddress((void**)&pq,   g_q);
    cudaGetSymbolAddress((void**)&pk,   g_k);
    cudaGetSymbolAddress((void**)&pv,   g_v);
    cudaGetSymbolAddress((void**)&pat,  g_att);
    cudaGetSymbolAddress((void**)&pt,   g_t);
    cudaGetSymbolAddress((void**)&ph,   g_h);
    cudaGetSymbolAddress((void**)&penc, g_enc);
    cudaGetSymbolAddress((void**)&ph1,  g_h1);
    cudaGetSymbolAddress((void**)&ph2,  g_h2);
    cudaGetSymbolAddress((void**)&pdec, g_dec);
    cudaGetSymbolAddress((void**)&pwp,  g_wp);
    cudaGetSymbolAddress((void**)&pdh,  g_dh);
    cudaGetSymbolAddress((void**)&pdl,  g_dl);
    cudaGetSymbolAddress((void**)&pw1h, g_w1h);
    cudaGetSymbolAddress((void**)&pw1l, g_w1l);
    cudaGetSymbolAddress((void**)&pah,  g_ah);
    cudaGetSymbolAddress((void**)&pw2h, g_w2h);
    cudaGetSymbolAddress((void**)&pw2l, g_w2l);

    cudaFuncSetAttribute(hgemm3_kernel,
                         cudaFuncAttributeMaxDynamicSharedMemorySize, 98304);
    cudaFuncSetAttribute(hgemm2_kernel,
                         cudaFuncAttributeMaxDynamicSharedMemorySize, 98304);

    // merged repack (one launch, so ncu -s 5 lands on a GEMM)
    repack9_kernel<<<dim3(512, 9), 512>>>(
        enc_wq, enc_wk, enc_wv, dec_swq, dec_swk, dec_swv,
        dec_cwq, dec_cwk, dec_cwv, pwp);

    // transpose+split classifier weights to K-major fp16 hi/lo
    tsplit_kernel<<<dim3(V1_ / 32, E_ / 32), 256>>>(cls_w1, pw1h, pw1l, E_, V1_);
    tsplit_kernel<<<dim3(V2_ / 32, V1_ / 32), 256>>>(cls_w2, pw2h, pw2l, V1_, V2_);

    // embeddings
    embed_kernel<<<dim3(S_, B_), 128>>>(src_ids, src_emb, px);
    embed_kernel<<<dim3(S_, B_), 128>>>(tgt_ids, tgt_emb, py);

    dim3 agrid(512, 64);
    const int WSZ = E_ * E_;

    // ----- encoder -----
    gemm(px, pwp + 0 * WSZ, nullptr, pq, BS_, 512, 512);
    gemm(px, pwp + 1 * WSZ, nullptr, pk, BS_, 512, 512);
    gemm(px, pwp + 2 * WSZ, nullptr, pv, BS_, 512, 512);
    attn_kernel<<<agrid, 128>>>(pq, pk, pv, pat, 1);
    gemm(pat, enc_dw, enc_db, pt, BS_, 512, 512);
    ln_kernel<<<BS_, 128>>>(px, pt, enc_ln_g, enc_ln_b, ph, 0);
    gemm(ph, enc_ffw, enc_ffb, pt, BS_, 512, 512);
    ln_kernel<<<BS_, 128>>>(ph, pt, enc_ln_g, enc_ln_b, penc, 0);

    // ----- decoder self-attention -----
    gemm(py, pwp + 3 * WSZ, nullptr, pq, BS_, 512, 512);
    gemm(py, pwp + 4 * WSZ, nullptr, pk, BS_, 512, 512);
    gemm(py, pwp + 5 * WSZ, nullptr, pv, BS_, 512, 512);
    attn_kernel<<<agrid, 128>>>(pq, pk, pv, pat, 1);
    gemm(pat, dec_sdw, dec_sdb, pt, BS_, 512, 512);
    ln_kernel<<<BS_, 128>>>(py, pt, dec_ln_g, dec_ln_b, ph1, 0);

    // ----- decoder cross-attention -----
    gemm(ph1,  pwp + 6 * WSZ, nullptr, pq, BS_, 512, 512);
    gemm(penc, pwp + 7 * WSZ, nullptr, pk, BS_, 512, 512);
    gemm(penc, pwp + 8 * WSZ, nullptr, pv, BS_, 512, 512);
    attn_kernel<<<agrid, 128>>>(pq, pk, pv, pat, 0);
    gemm(pat, dec_cdw, dec_cdb, pt, BS_, 512, 512);
    ln_kernel<<<BS_, 128>>>(ph1, pt, dec_ln_g, dec_ln_b, ph2, 0);

    // ----- decoder FF + final LN(relu) -----
    gemm(ph2, dec_ffw, dec_ffb, pt, BS_, 512, 512);
    ln_kernel<<<BS_, 128>>>(ph2, pt, dec_ln_g, dec_ln_b, pdec, 1);

    // ----- classifier -----
    split_kernel<<<1024, 256>>>(pdec, pdh, pdl, BS_ * E_);
    // cls1: 3-term (accuracy for hidden); epilogue relu -> fp16 hidden (hi only)
    hgemm3_kernel<<<(V1_ / 128) * 32, 256, 98304>>>(
        pdh, pdl, pw1h, pw1l, cls_b1, pah, V1_ / 128, V1_, E_);
    // cls2: 2-term (Ah@Bh + Ah@Bl), dominant GEMM, fp32 out
    hgemm2_kernel<<<((V2_ + 127) / 128) * 32, 256, 98304>>>(
        pah, pw2h, pw2l, cls_b2, out, (V2_ + 127) / 128, V2_, V1_);
}